// round 1
// baseline (speedup 1.0000x reference)
#include <cuda_runtime.h>
#include <math.h>

#define Bn 4
#define Cn 64
#define Hn 96
#define Wn 256
#define Mn 4
#define HW (Hn*Wn)
#define NPIX (Bn*Hn*Wn)
#define NELEM (NPIX*Cn)

// ------------------------ scratch (device globals; no alloc allowed) -------
__device__ float g_ln[2][NELEM];        // LayerNorm output, NHWC
__device__ float g_D[2][Mn*NELEM];      // dilated conv branches, [m][b][h][w][c]
__device__ float g_Q[2][NELEM];         // SKM output (attention Q), NHWC
__device__ float g_V[2][NELEM];         // 1x1 conv output (attention V), NHWC
__device__ float g_Z[2][Bn*Cn];         // pooled sums
__device__ float g_Sw[2][Bn*Mn*Cn];     // softmax branch weights
__device__ float g_wt[2][Mn*9*Cn*Cn];   // transposed weights [m][ky][kx][ci][co]

// ------------------------ zero pooled sums ---------------------------------
__global__ void zero_z_kernel() {
    int t = threadIdx.x;
    if (t < 2*Bn*Cn) (&g_Z[0][0])[t] = 0.f;
}

// ------------------------ weight transpose ---------------------------------
// src layout: [M][Cout][Cin][3][3]  ->  dst: [m][ky][kx][ci][co]
__global__ void wtrans_kernel(const float* __restrict__ ldw,
                              const float* __restrict__ rdw) {
    int t = blockIdx.x*blockDim.x + threadIdx.x;
    const int n = Mn*9*Cn*Cn;
    if (t >= 2*n) return;
    int side = t / n, i = t % n;
    const float* src = side ? rdw : ldw;
    int co = i & 63; int r = i >> 6;
    int ci = r & 63; r >>= 6;
    int kx = r % 3;  r /= 3;
    int ky = r % 3;  int m = r / 3;
    g_wt[side][i] = src[((((m*Cn + co)*Cn + ci)*3 + ky)*3 + kx)];
}

// ------------------------ LayerNorm2d: NCHW -> NHWC ------------------------
__global__ void ln_kernel(const float* __restrict__ x, const float* __restrict__ g,
                          const float* __restrict__ bia, int side) {
    __shared__ float xs[64*65];
    __shared__ float mu_s[64], rs_s[64];
    int w0 = blockIdx.x*64, h = blockIdx.y, b = blockIdx.z;
    int t = threadIdx.x;
    const float* xp = x + (size_t)b*Cn*HW + (size_t)h*Wn + w0;
    #pragma unroll
    for (int k = 0; k < 16; k++) {
        int lin = t + 256*k; int c = lin >> 6, p = lin & 63;
        xs[c*65 + p] = xp[(size_t)c*HW + p];
    }
    __syncthreads();
    if (t < 64) {
        float s = 0.f, s2 = 0.f;
        #pragma unroll
        for (int c = 0; c < 64; c++) { float v = xs[c*65 + t]; s += v; s2 += v*v; }
        float mu = s * (1.f/64.f);
        float var = s2 * (1.f/64.f) - mu*mu;
        mu_s[t] = mu; rs_s[t] = rsqrtf(var + 1e-6f);
    }
    __syncthreads();
    float* op = g_ln[side] + ((size_t)((b*Hn + h)*Wn + w0))*64;
    #pragma unroll
    for (int k = 0; k < 16; k++) {
        int lin = t + 256*k; int p = lin >> 6, c = lin & 63;
        op[p*64 + c] = (xs[c*65 + p] - mu_s[p]) * rs_s[p] * g[c] + bia[c];
    }
}

// ------------------------ 1x1 conv V: NCHW x -> NHWC V ---------------------
__global__ void v_kernel(const float* __restrict__ x, const float* __restrict__ w2,
                         const float* __restrict__ b2, int side) {
    __shared__ float xs[64*68];   // [ci][p]
    __shared__ float ws[64*68];   // [ci][co]
    int w0 = blockIdx.x*64, h = blockIdx.y, b = blockIdx.z;
    int t = threadIdx.x, tx = t & 15, ty = t >> 4;
    const float* xp = x + (size_t)b*Cn*HW + (size_t)h*Wn + w0;
    #pragma unroll
    for (int k = 0; k < 16; k++) {
        int lin = t + 256*k; int ci = lin >> 6, p = lin & 63;
        xs[ci*68 + p] = xp[(size_t)ci*HW + p];
    }
    #pragma unroll
    for (int k = 0; k < 16; k++) {
        int lin = t + 256*k; int co = lin >> 6, ci = lin & 63;
        ws[ci*68 + co] = w2[co*64 + ci];
    }
    __syncthreads();
    float acc[4][4];
    #pragma unroll
    for (int i = 0; i < 4; i++) { acc[i][0]=acc[i][1]=acc[i][2]=acc[i][3]=0.f; }
    #pragma unroll 4
    for (int ci = 0; ci < 64; ci++) {
        float4 av = *(const float4*)&xs[ci*68 + ty*4];
        float4 bv = *(const float4*)&ws[ci*68 + tx*4];
        acc[0][0] += av.x*bv.x; acc[0][1] += av.x*bv.y; acc[0][2] += av.x*bv.z; acc[0][3] += av.x*bv.w;
        acc[1][0] += av.y*bv.x; acc[1][1] += av.y*bv.y; acc[1][2] += av.y*bv.z; acc[1][3] += av.y*bv.w;
        acc[2][0] += av.z*bv.x; acc[2][1] += av.z*bv.y; acc[2][2] += av.z*bv.z; acc[2][3] += av.z*bv.w;
        acc[3][0] += av.w*bv.x; acc[3][1] += av.w*bv.y; acc[3][2] += av.w*bv.z; acc[3][3] += av.w*bv.w;
    }
    float4 bb = *(const float4*)&b2[tx*4];
    float* V = g_V[side];
    #pragma unroll
    for (int pj = 0; pj < 4; pj++) {
        int p = ty*4 + pj;
        float4 o; o.x = acc[pj][0]+bb.x; o.y = acc[pj][1]+bb.y;
                  o.z = acc[pj][2]+bb.z; o.w = acc[pj][3]+bb.w;
        *(float4*)&V[((size_t)((b*Hn + h)*Wn + w0 + p))*64 + tx*4] = o;
    }
}

// ------------------------ dilated 3x3 conv (implicit GEMM) -----------------
// grid (Wn/64, Hn, Bn*Mn); reads g_ln[side] NHWC, writes g_D[side], accumulates g_Z[side]
__global__ void conv_kernel(int side, const float* __restrict__ db) {
    __shared__ float xs[64*68];   // [p][ci]
    __shared__ float ws[64*68];   // [ci][co]
    __shared__ float zred[64];
    int w0 = blockIdx.x*64, h = blockIdx.y;
    int bm = blockIdx.z; int m = bm & 3, b = bm >> 2;
    int d = 2*(m+1);
    int t = threadIdx.x, tx = t & 15, ty = t >> 4;
    const float* ln = g_ln[side];
    const float* wt = g_wt[side];
    float acc[4][4];
    #pragma unroll
    for (int i = 0; i < 4; i++) { acc[i][0]=acc[i][1]=acc[i][2]=acc[i][3]=0.f; }

    for (int ky = 0; ky < 3; ky++) {
        int hy = h + (ky-1)*d;
        bool rok = ((unsigned)hy < (unsigned)Hn);
        for (int kx = 0; kx < 3; kx++) {
            __syncthreads();
            int sh = (kx-1)*d;
            #pragma unroll
            for (int k = 0; k < 4; k++) {
                int p = ty + k*16; int ci4 = tx;
                int col = w0 + sh + p;
                float4 v = make_float4(0.f,0.f,0.f,0.f);
                if (rok && (unsigned)col < (unsigned)Wn)
                    v = *(const float4*)&ln[((size_t)((b*Hn + hy)*Wn + col))*64 + ci4*4];
                *(float4*)&xs[p*68 + ci4*4] = v;
            }
            const float* tap = wt + (size_t)((m*9 + ky*3 + kx))*Cn*Cn;
            #pragma unroll
            for (int k = 0; k < 4; k++) {
                int lin = t + 256*k; int ci = lin >> 4, co4 = lin & 15;
                *(float4*)&ws[ci*68 + co4*4] = *(const float4*)&tap[ci*64 + co4*4];
            }
            __syncthreads();
            #pragma unroll 4
            for (int ci = 0; ci < 64; ci++) {
                float4 bv = *(const float4*)&ws[ci*68 + tx*4];
                float a0 = xs[(ty*4+0)*68 + ci];
                float a1 = xs[(ty*4+1)*68 + ci];
                float a2 = xs[(ty*4+2)*68 + ci];
                float a3 = xs[(ty*4+3)*68 + ci];
                acc[0][0] += a0*bv.x; acc[0][1] += a0*bv.y; acc[0][2] += a0*bv.z; acc[0][3] += a0*bv.w;
                acc[1][0] += a1*bv.x; acc[1][1] += a1*bv.y; acc[1][2] += a1*bv.z; acc[1][3] += a1*bv.w;
                acc[2][0] += a2*bv.x; acc[2][1] += a2*bv.y; acc[2][2] += a2*bv.z; acc[2][3] += a2*bv.w;
                acc[3][0] += a3*bv.x; acc[3][1] += a3*bv.y; acc[3][2] += a3*bv.z; acc[3][3] += a3*bv.w;
            }
        }
    }
    __syncthreads();
    if (t < 64) zred[t] = 0.f;
    __syncthreads();
    float4 bb = *(const float4*)&db[m*64 + tx*4];
    float* D = g_D[side];
    float zp0=0.f, zp1=0.f, zp2=0.f, zp3=0.f;
    #pragma unroll
    for (int pj = 0; pj < 4; pj++) {
        int p = ty*4 + pj;
        float4 o; o.x = acc[pj][0]+bb.x; o.y = acc[pj][1]+bb.y;
                  o.z = acc[pj][2]+bb.z; o.w = acc[pj][3]+bb.w;
        zp0 += o.x; zp1 += o.y; zp2 += o.z; zp3 += o.w;
        *(float4*)&D[(size_t)m*NELEM + ((size_t)((b*Hn + h)*Wn + w0 + p))*64 + tx*4] = o;
    }
    atomicAdd(&zred[tx*4+0], zp0);
    atomicAdd(&zred[tx*4+1], zp1);
    atomicAdd(&zred[tx*4+2], zp2);
    atomicAdd(&zred[tx*4+3], zp3);
    __syncthreads();
    if (t < 64) atomicAdd(&g_Z[side][b*64 + t], zred[t]);
}

// ------------------------ SKM gating: Z -> Sw ------------------------------
__global__ void sw_kernel(int side, const float* __restrict__ c1w,
                          const float* __restrict__ c1b, const float* __restrict__ pw) {
    __shared__ float Zn[64], S[128], lg[256], eb[256], mx[4], sm[4];
    int b = blockIdx.x, t = threadIdx.x;
    if (t < 64) Zn[t] = g_Z[side][b*64 + t] * (1.f/(float)HW);
    __syncthreads();
    if (t < 128) {
        float s = c1b[t];
        #pragma unroll 8
        for (int c = 0; c < 64; c++) s += Zn[c]*c1w[t*64 + c];
        S[t] = fmaxf(s, 0.f);
    }
    __syncthreads();
    {
        float s = 0.f;
        #pragma unroll 8
        for (int j = 0; j < 128; j++) s += S[j]*pw[j*256 + t];
        lg[t] = s;
    }
    __syncthreads();
    if (t < 4) {
        float m = -1e30f;
        for (int i = 0; i < 64; i++) m = fmaxf(m, lg[t*64 + i]);
        mx[t] = m;
    }
    __syncthreads();
    eb[t] = __expf(lg[t] - mx[t >> 6]);
    __syncthreads();
    if (t < 4) {
        float s = 0.f;
        for (int i = 0; i < 64; i++) s += eb[t*64 + i];
        sm[t] = s;
    }
    __syncthreads();
    g_Sw[side][b*256 + t] = eb[t] / sm[t >> 6];
}

// ------------------------ weighted branch combine: D,Sw -> Q ---------------
__global__ void combine_kernel(int side) {
    size_t idx = (size_t)blockIdx.x*256 + threadIdx.x;
    if (idx >= NELEM) return;
    int c = (int)(idx & 63);
    int b = (int)(idx / ((size_t)HW*64));
    const float* D = g_D[side];
    const float* Sw = g_Sw[side];
    float s = 0.f;
    #pragma unroll
    for (int m = 0; m < Mn; m++)
        s += Sw[b*256 + m*64 + c] * D[(size_t)m*NELEM + idx];
    g_Q[side][idx] = s;
}

// ------------------------ cross attention (one direction) ------------------
// out[b,c,h,w] = xres[b,c,h,w] + svec[c] * sum_v softmax_v(Qa[w]·Qb[v]*scale) * Vb[v,c]
__global__ void attn_kernel(int qa_side, const float* __restrict__ xres,
                            const float* __restrict__ svec, float* __restrict__ out) {
    extern __shared__ float smem[];
    float* Qbs = smem;                  // 256*65
    float* Vbs = Qbs + 256*65;          // 256*64
    float* qas = Vbs + 256*64;          // 8 warps * 256  ([warp][c*4+j])
    float* ps  = qas + 8*256;           // 8 warps * 1024 ([warp][v*4+r])
    int bh = blockIdx.x;
    int b = bh / Hn, h = bh % Hn;
    const float* Qap = g_Q[qa_side]     + (size_t)bh*Wn*64;
    const float* Qbp = g_Q[1 - qa_side] + (size_t)bh*Wn*64;
    const float* Vbp = g_V[1 - qa_side] + (size_t)bh*Wn*64;
    int t = threadIdx.x, lane = t & 31, warp = t >> 5;

    for (int k = 0; k < 64; k++) {
        int lin = t + 256*k;
        int v = lin >> 6, c = lin & 63;
        Qbs[v*65 + c] = Qbp[lin];
        Vbs[lin] = Vbp[lin];
    }
    __syncthreads();

    const float scale = 0.125f;   // 64^-0.5
    for (int grp = 0; grp < 8; grp++) {
        int rbase = warp*32 + grp*4;
        #pragma unroll
        for (int j = 0; j < 4; j++) {
            qas[warp*256 + lane*4 + j]        = Qap[(rbase+j)*64 + lane];
            qas[warp*256 + (lane+32)*4 + j]   = Qap[(rbase+j)*64 + lane + 32];
        }
        __syncwarp();
        float s[4][8];
        #pragma unroll
        for (int r = 0; r < 4; r++)
            #pragma unroll
            for (int j = 0; j < 8; j++) s[r][j] = 0.f;
        #pragma unroll 2
        for (int c = 0; c < 64; c++) {
            float4 q = *(const float4*)&qas[warp*256 + c*4];
            #pragma unroll
            for (int j = 0; j < 8; j++) {
                float qb = Qbs[(lane + 32*j)*65 + c];
                s[0][j] += q.x*qb; s[1][j] += q.y*qb;
                s[2][j] += q.z*qb; s[3][j] += q.w*qb;
            }
        }
        float p[4][8];
        #pragma unroll
        for (int r = 0; r < 4; r++) {
            float mx = -1e30f;
            #pragma unroll
            for (int j = 0; j < 8; j++) { s[r][j] *= scale; mx = fmaxf(mx, s[r][j]); }
            #pragma unroll
            for (int o = 16; o > 0; o >>= 1) mx = fmaxf(mx, __shfl_xor_sync(0xffffffffu, mx, o));
            float sum = 0.f;
            #pragma unroll
            for (int j = 0; j < 8; j++) { float e = __expf(s[r][j] - mx); p[r][j] = e; sum += e; }
            #pragma unroll
            for (int o = 16; o > 0; o >>= 1) sum += __shfl_xor_sync(0xffffffffu, sum, o);
            float inv = __frcp_rn(sum);
            #pragma unroll
            for (int j = 0; j < 8; j++) p[r][j] *= inv;
        }
        #pragma unroll
        for (int j = 0; j < 8; j++) {
            int v = lane + 32*j;
            float4 pv; pv.x = p[0][j]; pv.y = p[1][j]; pv.z = p[2][j]; pv.w = p[3][j];
            *(float4*)&ps[warp*1024 + v*4] = pv;
        }
        __syncwarp();
        float o00=0,o01=0,o10=0,o11=0,o20=0,o21=0,o30=0,o31=0;
        int c0 = lane*2;
        #pragma unroll 4
        for (int v = 0; v < 256; v++) {
            float4 pv = *(const float4*)&ps[warp*1024 + v*4];
            float2 vb = *(const float2*)&Vbs[v*64 + c0];
            o00 += pv.x*vb.x; o01 += pv.x*vb.y;
            o10 += pv.y*vb.x; o11 += pv.y*vb.y;
            o20 += pv.z*vb.x; o21 += pv.z*vb.y;
            o30 += pv.w*vb.x; o31 += pv.w*vb.y;
        }
        float sc0 = svec[c0], sc1 = svec[c0+1];
        float ro[4][2] = {{o00,o01},{o10,o11},{o20,o21},{o30,o31}};
        #pragma unroll
        for (int r = 0; r < 4; r++) {
            int w = rbase + r;
            size_t i0 = ((size_t)(b*64 + c0)*Hn + h)*Wn + w;
            out[i0] = xres[i0] + sc0*ro[r][0];
            size_t i1 = i0 + (size_t)HW;
            out[i1] = xres[i1] + sc1*ro[r][1];
        }
    }
}

// ------------------------ launch -------------------------------------------
extern "C" void kernel_launch(void* const* d_in, const int* in_sizes, int n_in,
                              void* d_out, int out_size) {
    const float* x_l   = (const float*)d_in[0];
    const float* x_r   = (const float*)d_in[1];
    const float* lnl_g = (const float*)d_in[2];
    const float* lnl_b = (const float*)d_in[3];
    const float* lnr_g = (const float*)d_in[4];
    const float* lnr_b = (const float*)d_in[5];
    const float* l_dw  = (const float*)d_in[6];
    const float* l_db  = (const float*)d_in[7];
    const float* l_c1w = (const float*)d_in[8];
    const float* l_c1b = (const float*)d_in[9];
    const float* l_pw  = (const float*)d_in[10];
    const float* r_dw  = (const float*)d_in[11];
    const float* r_db  = (const float*)d_in[12];
    const float* r_c1w = (const float*)d_in[13];
    const float* r_c1b = (const float*)d_in[14];
    const float* r_pw  = (const float*)d_in[15];
    const float* l2w   = (const float*)d_in[16];
    const float* l2b   = (const float*)d_in[17];
    const float* r2w   = (const float*)d_in[18];
    const float* r2b   = (const float*)d_in[19];
    const float* beta  = (const float*)d_in[20];
    const float* gamma = (const float*)d_in[21];
    float* out_l = (float*)d_out;
    float* out_r = out_l + (size_t)NELEM;

    static bool attr_set = false;
    (void)attr_set;
    const int attn_smem = (256*65 + 256*64 + 8*256 + 8*1024) * 4;
    cudaFuncSetAttribute(attn_kernel, cudaFuncAttributeMaxDynamicSharedMemorySize, attn_smem);

    zero_z_kernel<<<1, 512>>>();
    wtrans_kernel<<<(2*Mn*9*Cn*Cn + 255)/256, 256>>>(l_dw, r_dw);

    dim3 tgrid(Wn/64, Hn, Bn);
    ln_kernel<<<tgrid, 256>>>(x_l, lnl_g, lnl_b, 0);
    ln_kernel<<<tgrid, 256>>>(x_r, lnr_g, lnr_b, 1);
    v_kernel<<<tgrid, 256>>>(x_l, l2w, l2b, 0);
    v_kernel<<<tgrid, 256>>>(x_r, r2w, r2b, 1);

    dim3 cgrid(Wn/64, Hn, Bn*Mn);
    conv_kernel<<<cgrid, 256>>>(0, l_db);
    conv_kernel<<<cgrid, 256>>>(1, r_db);

    sw_kernel<<<Bn, 256>>>(0, l_c1w, l_c1b, l_pw);
    sw_kernel<<<Bn, 256>>>(1, r_c1w, r_c1b, r_pw);

    combine_kernel<<<(NELEM + 255)/256, 256>>>(0);
    combine_kernel<<<(NELEM + 255)/256, 256>>>(1);

    attn_kernel<<<Bn*Hn, 256, attn_smem>>>(0, x_l, beta,  out_l);
    attn_kernel<<<Bn*Hn, 256, attn_smem>>>(1, x_r, gamma, out_r);
}

// round 2
// speedup vs baseline: 1.0757x; 1.0757x over previous
#include <cuda_runtime.h>
#include <math.h>

#define Bn 4
#define Cn 64
#define Hn 96
#define Wn 256
#define Mn 4
#define HW (Hn*Wn)
#define NPIX (Bn*Hn*Wn)
#define NELEM (NPIX*Cn)

typedef unsigned long long ull;

__device__ __forceinline__ ull pk2(float a, float b) {
    ull r; asm("mov.b64 %0, {%1,%2};" : "=l"(r) : "f"(a), "f"(b)); return r;
}
__device__ __forceinline__ void fma2(ull& d, ull a, ull b) {
    asm("fma.rn.f32x2 %0, %1, %2, %3;" : "=l"(d) : "l"(a), "l"(b), "l"(d));
}
__device__ __forceinline__ float2 unpk(ull v) {
    float2 f; asm("mov.b64 {%0,%1}, %2;" : "=f"(f.x), "=f"(f.y) : "l"(v)); return f;
}

// ------------------------ scratch (device globals; no alloc allowed) -------
__device__ float g_ln[2][NELEM];        // LayerNorm output, [b][h][c][w]
__device__ float g_D[2][Mn*NELEM];      // dilated conv branches, [m][b][h][w][c]
__device__ float g_Q[2][NELEM];         // SKM output (attention Q), NHWC
__device__ float g_V[2][NELEM];         // 1x1 conv output (attention V), NHWC
__device__ float g_Z[2][Bn*Cn];         // pooled sums
__device__ float g_Sw[2][Bn*Mn*Cn];     // softmax branch weights
__device__ float g_wt[2][Mn*9*Cn*Cn];   // transposed weights [m][ky][kx][ci][co]

// ------------------------ zero pooled sums ---------------------------------
__global__ void zero_z_kernel() {
    int t = threadIdx.x;
    if (t < 2*Bn*Cn) (&g_Z[0][0])[t] = 0.f;
}

// ------------------------ weight transpose ---------------------------------
// src layout: [M][Cout][Cin][3][3]  ->  dst: [m][ky][kx][ci][co]
__global__ void wtrans_kernel(const float* __restrict__ ldw,
                              const float* __restrict__ rdw) {
    int t = blockIdx.x*blockDim.x + threadIdx.x;
    const int n = Mn*9*Cn*Cn;
    if (t >= 2*n) return;
    int side = t / n, i = t % n;
    const float* src = side ? rdw : ldw;
    int co = i & 63; int r = i >> 6;
    int ci = r & 63; r >>= 6;
    int kx = r % 3;  r /= 3;
    int ky = r % 3;  int m = r / 3;
    g_wt[side][i] = src[((((m*Cn + co)*Cn + ci)*3 + ky)*3 + kx)];
}

// ------------------------ LayerNorm2d: NCHW -> [b][h][c][w] ----------------
__global__ void ln_kernel(const float* __restrict__ x, const float* __restrict__ g,
                          const float* __restrict__ bia, int side) {
    __shared__ float xs[64*65];
    __shared__ float mu_s[64], rs_s[64];
    int w0 = blockIdx.x*64, h = blockIdx.y, b = blockIdx.z;
    int t = threadIdx.x;
    const float* xp = x + (size_t)b*Cn*HW + (size_t)h*Wn + w0;
    #pragma unroll
    for (int k = 0; k < 16; k++) {
        int lin = t + 256*k; int c = lin >> 6, p = lin & 63;
        xs[c*65 + p] = xp[(size_t)c*HW + p];
    }
    __syncthreads();
    if (t < 64) {
        float s = 0.f, s2 = 0.f;
        #pragma unroll
        for (int c = 0; c < 64; c++) { float v = xs[c*65 + t]; s += v; s2 += v*v; }
        float mu = s * (1.f/64.f);
        float var = s2 * (1.f/64.f) - mu*mu;
        mu_s[t] = mu; rs_s[t] = rsqrtf(var + 1e-6f);
    }
    __syncthreads();
    float* op = g_ln[side] + ((size_t)(b*Hn + h))*64*Wn + w0;
    #pragma unroll
    for (int k = 0; k < 16; k++) {
        int lin = t + 256*k; int c = lin >> 6, p = lin & 63;
        op[(size_t)c*Wn + p] = (xs[c*65 + p] - mu_s[p]) * rs_s[p] * g[c] + bia[c];
    }
}

// ------------------------ 1x1 conv V: NCHW x -> NHWC V (f32x2) -------------
__global__ void v_kernel(const float* __restrict__ x, const float* __restrict__ w2,
                         const float* __restrict__ b2, int side) {
    __shared__ float xs[64*68];   // [ci][p]
    __shared__ float ws[64*68];   // [ci][co]
    int w0 = blockIdx.x*64, h = blockIdx.y, b = blockIdx.z;
    int t = threadIdx.x, tx = t & 15, ty = t >> 4;
    const float* xp = x + (size_t)b*Cn*HW + (size_t)h*Wn + w0;
    #pragma unroll
    for (int k = 0; k < 16; k++) {
        int lin = t + 256*k; int ci = lin >> 6, p = lin & 63;
        xs[ci*68 + p] = xp[(size_t)ci*HW + p];
    }
    #pragma unroll
    for (int k = 0; k < 16; k++) {
        int lin = t + 256*k; int co = lin >> 6, ci = lin & 63;
        ws[ci*68 + co] = w2[co*64 + ci];
    }
    __syncthreads();
    ull acc[4][2];
    #pragma unroll
    for (int i = 0; i < 4; i++) { acc[i][0] = 0ull; acc[i][1] = 0ull; }
    #pragma unroll 8
    for (int ci = 0; ci < 64; ci++) {
        float4 av = *(const float4*)&xs[ci*68 + ty*4];
        ulonglong2 bb = *(const ulonglong2*)&ws[ci*68 + tx*4];
        ull p0 = pk2(av.x, av.x), p1 = pk2(av.y, av.y);
        ull p2 = pk2(av.z, av.z), p3 = pk2(av.w, av.w);
        fma2(acc[0][0], p0, bb.x); fma2(acc[0][1], p0, bb.y);
        fma2(acc[1][0], p1, bb.x); fma2(acc[1][1], p1, bb.y);
        fma2(acc[2][0], p2, bb.x); fma2(acc[2][1], p2, bb.y);
        fma2(acc[3][0], p3, bb.x); fma2(acc[3][1], p3, bb.y);
    }
    float4 bb4 = *(const float4*)&b2[tx*4];
    float* V = g_V[side];
    #pragma unroll
    for (int pj = 0; pj < 4; pj++) {
        int p = ty*4 + pj;
        float2 o01 = unpk(acc[pj][0]);
        float2 o23 = unpk(acc[pj][1]);
        float4 o; o.x = o01.x+bb4.x; o.y = o01.y+bb4.y;
                  o.z = o23.x+bb4.z; o.w = o23.y+bb4.w;
        *(float4*)&V[((size_t)((b*Hn + h)*Wn + w0 + p))*64 + tx*4] = o;
    }
}

// ------------------------ dilated 3x3 conv (implicit GEMM, f32x2) ----------
// reads g_ln[side] ([b][h][c][w]), writes g_D[side] NHWC, accumulates g_Z
#define XS_STRIDE 84
__global__ void conv_kernel(int side, const float* __restrict__ db) {
    __shared__ float xs[64*XS_STRIDE];  // [ci][strip col]
    __shared__ float ws[64*68];         // [ci][co]
    __shared__ float zred[64];
    int w0 = blockIdx.x*64, h = blockIdx.y;
    int bm = blockIdx.z; int m = bm & 3, b = bm >> 2;
    int d = 2*(m+1);
    int wdt = 64 + 2*d;
    int t = threadIdx.x, tx = t & 15, ty = t >> 4;
    int lane = t & 31, warp = t >> 5;
    const float* ln = g_ln[side];
    const float* wt = g_wt[side] + (size_t)m*9*Cn*Cn;
    ull acc[4][2];
    #pragma unroll
    for (int i = 0; i < 4; i++) { acc[i][0] = 0ull; acc[i][1] = 0ull; }

    for (int ky = 0; ky < 3; ky++) {
        int hy = h + (ky-1)*d;
        if ((unsigned)hy >= (unsigned)Hn) continue;   // zero-pad row: contributes 0
        __syncthreads();
        // load input strip: cols [w0-d, w0+63+d], layout [ci][col]
        const float* rowbase = ln + ((size_t)(b*Hn + hy))*64*Wn;
        for (int ci = warp; ci < 64; ci += 8) {
            const float* rp = rowbase + (size_t)ci*Wn;
            for (int col2 = lane; col2*2 < wdt; col2 += 32) {
                int gc = w0 - d + col2*2;
                float v0 = ((unsigned)gc     < (unsigned)Wn) ? rp[gc]   : 0.f;
                float v1 = ((unsigned)(gc+1) < (unsigned)Wn) ? rp[gc+1] : 0.f;
                *(float2*)&xs[ci*XS_STRIDE + col2*2] = make_float2(v0, v1);
            }
        }
        for (int kx = 0; kx < 3; kx++) {
            __syncthreads();
            const float* tap = wt + (size_t)(ky*3 + kx)*Cn*Cn;
            #pragma unroll
            for (int k = 0; k < 4; k++) {
                int lin = t + 256*k; int ci = lin >> 4, co4 = lin & 15;
                *(float4*)&ws[ci*68 + co4*4] = *(const float4*)&tap[ci*64 + co4*4];
            }
            __syncthreads();
            int coff = kx*d + ty*4;
            #pragma unroll 8
            for (int ci = 0; ci < 64; ci++) {
                float2 a01 = *(const float2*)&xs[ci*XS_STRIDE + coff];
                float2 a23 = *(const float2*)&xs[ci*XS_STRIDE + coff + 2];
                ulonglong2 bb = *(const ulonglong2*)&ws[ci*68 + tx*4];
                ull p0 = pk2(a01.x, a01.x), p1 = pk2(a01.y, a01.y);
                ull p2 = pk2(a23.x, a23.x), p3 = pk2(a23.y, a23.y);
                fma2(acc[0][0], p0, bb.x); fma2(acc[0][1], p0, bb.y);
                fma2(acc[1][0], p1, bb.x); fma2(acc[1][1], p1, bb.y);
                fma2(acc[2][0], p2, bb.x); fma2(acc[2][1], p2, bb.y);
                fma2(acc[3][0], p3, bb.x); fma2(acc[3][1], p3, bb.y);
            }
        }
    }
    __syncthreads();
    if (t < 64) zred[t] = 0.f;
    __syncthreads();
    float4 bb4 = *(const float4*)&db[m*64 + tx*4];
    float* D = g_D[side];
    float zp0=0.f, zp1=0.f, zp2=0.f, zp3=0.f;
    #pragma unroll
    for (int pj = 0; pj < 4; pj++) {
        int p = ty*4 + pj;
        float2 o01 = unpk(acc[pj][0]);
        float2 o23 = unpk(acc[pj][1]);
        float4 o; o.x = o01.x+bb4.x; o.y = o01.y+bb4.y;
                  o.z = o23.x+bb4.z; o.w = o23.y+bb4.w;
        zp0 += o.x; zp1 += o.y; zp2 += o.z; zp3 += o.w;
        *(float4*)&D[(size_t)m*NELEM + ((size_t)((b*Hn + h)*Wn + w0 + p))*64 + tx*4] = o;
    }
    atomicAdd(&zred[tx*4+0], zp0);
    atomicAdd(&zred[tx*4+1], zp1);
    atomicAdd(&zred[tx*4+2], zp2);
    atomicAdd(&zred[tx*4+3], zp3);
    __syncthreads();
    if (t < 64) atomicAdd(&g_Z[side][b*64 + t], zred[t]);
}

// ------------------------ SKM gating: Z -> Sw ------------------------------
__global__ void sw_kernel(int side, const float* __restrict__ c1w,
                          const float* __restrict__ c1b, const float* __restrict__ pw) {
    __shared__ float Zn[64], S[128], lg[256], eb[256], mx[4], sm[4];
    int b = blockIdx.x, t = threadIdx.x;
    if (t < 64) Zn[t] = g_Z[side][b*64 + t] * (1.f/(float)HW);
    __syncthreads();
    if (t < 128) {
        float s = c1b[t];
        #pragma unroll 8
        for (int c = 0; c < 64; c++) s += Zn[c]*c1w[t*64 + c];
        S[t] = fmaxf(s, 0.f);
    }
    __syncthreads();
    {
        float s = 0.f;
        #pragma unroll 8
        for (int j = 0; j < 128; j++) s += S[j]*pw[j*256 + t];
        lg[t] = s;
    }
    __syncthreads();
    if (t < 4) {
        float m = -1e30f;
        for (int i = 0; i < 64; i++) m = fmaxf(m, lg[t*64 + i]);
        mx[t] = m;
    }
    __syncthreads();
    eb[t] = __expf(lg[t] - mx[t >> 6]);
    __syncthreads();
    if (t < 4) {
        float s = 0.f;
        for (int i = 0; i < 64; i++) s += eb[t*64 + i];
        sm[t] = s;
    }
    __syncthreads();
    g_Sw[side][b*256 + t] = eb[t] / sm[t >> 6];
}

// ------------------------ weighted branch combine: D,Sw -> Q ---------------
__global__ void combine_kernel(int side) {
    size_t idx = (size_t)blockIdx.x*256 + threadIdx.x;
    if (idx >= NELEM) return;
    int c = (int)(idx & 63);
    int b = (int)(idx / ((size_t)HW*64));
    const float* D = g_D[side];
    const float* Sw = g_Sw[side];
    float s = 0.f;
    #pragma unroll
    for (int m = 0; m < Mn; m++)
        s += Sw[b*256 + m*64 + c] * D[(size_t)m*NELEM + idx];
    g_Q[side][idx] = s;
}

// ------------------------ cross attention (one direction, f32x2) -----------
// out[b,c,h,w] = xres[b,c,h,w] + svec[c] * sum_v softmax_v(Qa[w]·Qb[v]*scale) * Vb[v,c]
__global__ void attn_kernel(int qa_side, const float* __restrict__ xres,
                            const float* __restrict__ svec, float* __restrict__ out) {
    extern __shared__ float smem[];
    float* Qbs = smem;                  // 256*66  [v][c]
    float* Vbs = Qbs + 256*66;          // 256*64  [v][c]
    float* qas = Vbs + 256*64;          // 8 warps * 256  ([warp][c*4+r])
    float* ps  = qas + 8*256;           // 8 warps * 1024 ([warp][v*4+r])
    int bh = blockIdx.x;
    int b = bh / Hn, h = bh % Hn;
    const float* Qap = g_Q[qa_side]     + (size_t)bh*Wn*64;
    const float* Qbp = g_Q[1 - qa_side] + (size_t)bh*Wn*64;
    const float* Vbp = g_V[1 - qa_side] + (size_t)bh*Wn*64;
    int t = threadIdx.x, lane = t & 31, warp = t >> 5;

    for (int k = 0; k < 64; k++) {
        int lin = t + 256*k;
        int v = lin >> 6, c = lin & 63;
        Qbs[v*66 + c] = Qbp[lin];
        Vbs[lin] = Vbp[lin];
    }
    __syncthreads();

    const float scale = 0.125f;   // 64^-0.5
    for (int grp = 0; grp < 8; grp++) {
        int rbase = warp*32 + grp*4;
        #pragma unroll
        for (int j = 0; j < 4; j++) {
            qas[warp*256 + lane*4 + j]        = Qap[(rbase+j)*64 + lane];
            qas[warp*256 + (lane+32)*4 + j]   = Qap[(rbase+j)*64 + lane + 32];
        }
        __syncwarp();
        // QK^T: accumulate f32x2 pairs over (even c, odd c)
        ull sp[4][8];
        #pragma unroll
        for (int r = 0; r < 4; r++)
            #pragma unroll
            for (int j = 0; j < 8; j++) sp[r][j] = 0ull;
        #pragma unroll 4
        for (int cc = 0; cc < 64; cc += 2) {
            float4 fa = *(const float4*)&qas[warp*256 + cc*4];
            float4 fb = *(const float4*)&qas[warp*256 + (cc+1)*4];
            ull q0 = pk2(fa.x, fb.x), q1 = pk2(fa.y, fb.y);
            ull q2 = pk2(fa.z, fb.z), q3 = pk2(fa.w, fb.w);
            #pragma unroll
            for (int j = 0; j < 8; j++) {
                ull qb2 = *(const ull*)&Qbs[(lane + 32*j)*66 + cc];
                fma2(sp[0][j], q0, qb2);
                fma2(sp[1][j], q1, qb2);
                fma2(sp[2][j], q2, qb2);
                fma2(sp[3][j], q3, qb2);
            }
        }
        float s[4][8];
        #pragma unroll
        for (int r = 0; r < 4; r++)
            #pragma unroll
            for (int j = 0; j < 8; j++) {
                float2 u = unpk(sp[r][j]);
                s[r][j] = u.x + u.y;
            }
        float p[4][8];
        #pragma unroll
        for (int r = 0; r < 4; r++) {
            float mx = -1e30f;
            #pragma unroll
            for (int j = 0; j < 8; j++) { s[r][j] *= scale; mx = fmaxf(mx, s[r][j]); }
            #pragma unroll
            for (int o = 16; o > 0; o >>= 1) mx = fmaxf(mx, __shfl_xor_sync(0xffffffffu, mx, o));
            float sum = 0.f;
            #pragma unroll
            for (int j = 0; j < 8; j++) { float e = __expf(s[r][j] - mx); p[r][j] = e; sum += e; }
            #pragma unroll
            for (int o = 16; o > 0; o >>= 1) sum += __shfl_xor_sync(0xffffffffu, sum, o);
            float inv = __frcp_rn(sum);
            #pragma unroll
            for (int j = 0; j < 8; j++) p[r][j] *= inv;
        }
        #pragma unroll
        for (int j = 0; j < 8; j++) {
            int v = lane + 32*j;
            float4 pv; pv.x = p[0][j]; pv.y = p[1][j]; pv.z = p[2][j]; pv.w = p[3][j];
            *(float4*)&ps[warp*1024 + v*4] = pv;
        }
        __syncwarp();
        // P·V: accumulate f32x2 pairs over channel pair (c0, c0+1)
        int c0 = lane*2;
        ull o0 = 0ull, o1 = 0ull, o2 = 0ull, o3 = 0ull;
        #pragma unroll 8
        for (int v = 0; v < 256; v++) {
            float4 pv = *(const float4*)&ps[warp*1024 + v*4];
            ull vb = *(const ull*)&Vbs[v*64 + c0];
            ull w0p = pk2(pv.x, pv.x), w1p = pk2(pv.y, pv.y);
            ull w2p = pk2(pv.z, pv.z), w3p = pk2(pv.w, pv.w);
            fma2(o0, w0p, vb);
            fma2(o1, w1p, vb);
            fma2(o2, w2p, vb);
            fma2(o3, w3p, vb);
        }
        float2 r0 = unpk(o0), r1 = unpk(o1), r2 = unpk(o2), r3 = unpk(o3);
        float sc0 = svec[c0], sc1 = svec[c0+1];
        float ro[4][2] = {{r0.x,r0.y},{r1.x,r1.y},{r2.x,r2.y},{r3.x,r3.y}};
        #pragma unroll
        for (int r = 0; r < 4; r++) {
            int w = rbase + r;
            size_t i0 = ((size_t)(b*64 + c0)*Hn + h)*Wn + w;
            out[i0] = xres[i0] + sc0*ro[r][0];
            size_t i1 = i0 + (size_t)HW;
            out[i1] = xres[i1] + sc1*ro[r][1];
        }
    }
}

// ------------------------ launch -------------------------------------------
extern "C" void kernel_launch(void* const* d_in, const int* in_sizes, int n_in,
                              void* d_out, int out_size) {
    const float* x_l   = (const float*)d_in[0];
    const float* x_r   = (const float*)d_in[1];
    const float* lnl_g = (const float*)d_in[2];
    const float* lnl_b = (const float*)d_in[3];
    const float* lnr_g = (const float*)d_in[4];
    const float* lnr_b = (const float*)d_in[5];
    const float* l_dw  = (const float*)d_in[6];
    const float* l_db  = (const float*)d_in[7];
    const float* l_c1w = (const float*)d_in[8];
    const float* l_c1b = (const float*)d_in[9];
    const float* l_pw  = (const float*)d_in[10];
    const float* r_dw  = (const float*)d_in[11];
    const float* r_db  = (const float*)d_in[12];
    const float* r_c1w = (const float*)d_in[13];
    const float* r_c1b = (const float*)d_in[14];
    const float* r_pw  = (const float*)d_in[15];
    const float* l2w   = (const float*)d_in[16];
    const float* l2b   = (const float*)d_in[17];
    const float* r2w   = (const float*)d_in[18];
    const float* r2b   = (const float*)d_in[19];
    const float* beta  = (const float*)d_in[20];
    const float* gamma = (const float*)d_in[21];
    float* out_l = (float*)d_out;
    float* out_r = out_l + (size_t)NELEM;

    const int attn_smem = (256*66 + 256*64 + 8*256 + 8*1024) * 4;
    cudaFuncSetAttribute(attn_kernel, cudaFuncAttributeMaxDynamicSharedMemorySize, attn_smem);

    zero_z_kernel<<<1, 512>>>();
    wtrans_kernel<<<(2*Mn*9*Cn*Cn + 255)/256, 256>>>(l_dw, r_dw);

    dim3 tgrid(Wn/64, Hn, Bn);
    ln_kernel<<<tgrid, 256>>>(x_l, lnl_g, lnl_b, 0);
    ln_kernel<<<tgrid, 256>>>(x_r, lnr_g, lnr_b, 1);
    v_kernel<<<tgrid, 256>>>(x_l, l2w, l2b, 0);
    v_kernel<<<tgrid, 256>>>(x_r, r2w, r2b, 1);

    dim3 cgrid(Wn/64, Hn, Bn*Mn);
    conv_kernel<<<cgrid, 256>>>(0, l_db);
    conv_kernel<<<cgrid, 256>>>(1, r_db);

    sw_kernel<<<Bn, 256>>>(0, l_c1w, l_c1b, l_pw);
    sw_kernel<<<Bn, 256>>>(1, r_c1w, r_c1b, r_pw);

    combine_kernel<<<(NELEM + 255)/256, 256>>>(0);
    combine_kernel<<<(NELEM + 255)/256, 256>>>(1);

    attn_kernel<<<Bn*Hn, 256, attn_smem>>>(0, x_l, beta,  out_l);
    attn_kernel<<<Bn*Hn, 256, attn_smem>>>(1, x_r, gamma, out_r);
}

// round 4
// speedup vs baseline: 1.8154x; 1.6876x over previous
#include <cuda_runtime.h>
#include <cuda_bf16.h>
#include <math.h>
#include <cstdint>

#define Bn 4
#define Cn 64
#define Hn 96
#define Wn 256
#define Mn 4
#define HW (Hn*Wn)
#define NPIX (Bn*Hn*Wn)
#define NELEM (NPIX*Cn)

typedef unsigned long long ull;

// ---------------- f32x2 helpers (attention / V path) -----------------------
__device__ __forceinline__ ull pk2(float a, float b) {
    ull r; asm("mov.b64 %0, {%1,%2};" : "=l"(r) : "f"(a), "f"(b)); return r;
}
__device__ __forceinline__ void fma2(ull& d, ull a, ull b) {
    asm("fma.rn.f32x2 %0, %1, %2, %3;" : "=l"(d) : "l"(a), "l"(b), "l"(d));
}
__device__ __forceinline__ float2 unpk(ull v) {
    float2 f; asm("mov.b64 {%0,%1}, %2;" : "=f"(f.x), "=f"(f.y) : "l"(v)); return f;
}

// ---------------- mma.sync helpers -----------------------------------------
__device__ __forceinline__ uint32_t smem_u32(const void* p) {
    uint32_t a;
    asm("{ .reg .u64 t; cvta.to.shared.u64 t, %1; cvt.u32.u64 %0, t; }" : "=r"(a) : "l"(p));
    return a;
}
#define LDSM4(r, addr) \
    asm volatile("ldmatrix.sync.aligned.m8n8.x4.shared.b16 {%0,%1,%2,%3}, [%4];" \
        : "=r"((r)[0]), "=r"((r)[1]), "=r"((r)[2]), "=r"((r)[3]) : "r"(addr))
#define MMA_BF16(ac, a, b0_, b1_) \
    asm volatile("mma.sync.aligned.m16n8k16.row.col.f32.bf16.bf16.f32 " \
        "{%0,%1,%2,%3},{%4,%5,%6,%7},{%8,%9},{%0,%1,%2,%3};" \
        : "+f"((ac)[0]), "+f"((ac)[1]), "+f"((ac)[2]), "+f"((ac)[3]) \
        : "r"((a)[0]), "r"((a)[1]), "r"((a)[2]), "r"((a)[3]), "r"(b0_), "r"(b1_))

// ---------------- scratch (device globals) ---------------------------------
__device__ __nv_bfloat16 g_lnh[2][NELEM];     // LN out hi, NHWC
__device__ __nv_bfloat16 g_lnl[2][NELEM];     // LN out lo, NHWC
__device__ __nv_bfloat16 g_w2[2*4*9*2*4096];  // weights [side][m][tap][split][co][ci]
__device__ float g_D[2][Mn*NELEM];            // conv branches NHWC
__device__ float g_Q[2][NELEM];               // SKM output NHWC
__device__ float g_V[2][NELEM];               // V NHWC
__device__ float g_Z[2][Bn*Cn];
__device__ float g_Sw[2][Bn*Mn*Cn];

// ---------------- zero pooled sums -----------------------------------------
__global__ void zero_z_kernel() {
    int t = threadIdx.x;
    if (t < 2*Bn*Cn) (&g_Z[0][0])[t] = 0.f;
}

// ---------------- weight transform: split bf16, [co][ci] tiles --------------
// src: [M][Co][Ci][3][3]
__global__ void wtrans_kernel(const float* __restrict__ ldw,
                              const float* __restrict__ rdw) {
    int t = blockIdx.x*blockDim.x + threadIdx.x;
    const int n = Mn*9*Cn*Cn;
    if (t >= 2*n) return;
    int side = t / n, i = t % n;
    const float* src = side ? rdw : ldw;
    int ci = i & 63; int r = i >> 6;
    int co = r & 63; r >>= 6;
    int tap = r % 9; int m = r / 9;
    int ky = tap / 3, kx = tap % 3;
    float wv = src[((((m*Cn + co)*Cn + ci)*3 + ky)*3 + kx)];
    __nv_bfloat16 hi = __float2bfloat16(wv);
    __nv_bfloat16 lo = __float2bfloat16(wv - __bfloat162float(hi));
    size_t base = (size_t)(((side*4 + m)*9 + tap)*2)*4096 + co*64 + ci;
    g_w2[base] = hi;
    g_w2[base + 4096] = lo;
}

// ---------------- LayerNorm2d: NCHW -> bf16 hi/lo NHWC ---------------------
__global__ void ln_kernel(const float* __restrict__ x, const float* __restrict__ g,
                          const float* __restrict__ bia, int side) {
    __shared__ float xs[64*65];
    __shared__ float mu_s[64], rs_s[64];
    int w0 = blockIdx.x*64, h = blockIdx.y, b = blockIdx.z;
    int t = threadIdx.x;
    const float* xp = x + (size_t)b*Cn*HW + (size_t)h*Wn + w0;
    #pragma unroll
    for (int k = 0; k < 16; k++) {
        int lin = t + 256*k; int c = lin >> 6, p = lin & 63;
        xs[c*65 + p] = xp[(size_t)c*HW + p];
    }
    __syncthreads();
    if (t < 64) {
        float s = 0.f, s2 = 0.f;
        #pragma unroll
        for (int c = 0; c < 64; c++) { float v = xs[c*65 + t]; s += v; s2 += v*v; }
        float mu = s * (1.f/64.f);
        float var = s2 * (1.f/64.f) - mu*mu;
        mu_s[t] = mu; rs_s[t] = rsqrtf(var + 1e-6f);
    }
    __syncthreads();
    size_t obase = ((size_t)((b*Hn + h)*Wn + w0))*64;
    __nv_bfloat16* oh = g_lnh[side] + obase;
    __nv_bfloat16* ol = g_lnl[side] + obase;
    #pragma unroll
    for (int k = 0; k < 16; k++) {
        int lin = t + 256*k; int p = lin >> 6, c = lin & 63;
        float v = (xs[c*65 + p] - mu_s[p]) * rs_s[p] * g[c] + bia[c];
        __nv_bfloat16 hi = __float2bfloat16(v);
        oh[p*64 + c] = hi;
        ol[p*64 + c] = __float2bfloat16(v - __bfloat162float(hi));
    }
}

// ---------------- 1x1 conv V (f32x2) ---------------------------------------
__global__ void v_kernel(const float* __restrict__ x, const float* __restrict__ w2,
                         const float* __restrict__ b2, int side) {
    __shared__ float xs[64*68];
    __shared__ float ws[64*68];
    int w0 = blockIdx.x*64, h = blockIdx.y, b = blockIdx.z;
    int t = threadIdx.x, tx = t & 15, ty = t >> 4;
    const float* xp = x + (size_t)b*Cn*HW + (size_t)h*Wn + w0;
    #pragma unroll
    for (int k = 0; k < 16; k++) {
        int lin = t + 256*k; int ci = lin >> 6, p = lin & 63;
        xs[ci*68 + p] = xp[(size_t)ci*HW + p];
    }
    #pragma unroll
    for (int k = 0; k < 16; k++) {
        int lin = t + 256*k; int co = lin >> 6, ci = lin & 63;
        ws[ci*68 + co] = w2[co*64 + ci];
    }
    __syncthreads();
    ull acc[4][2];
    #pragma unroll
    for (int i = 0; i < 4; i++) { acc[i][0] = 0ull; acc[i][1] = 0ull; }
    #pragma unroll 8
    for (int ci = 0; ci < 64; ci++) {
        float4 av = *(const float4*)&xs[ci*68 + ty*4];
        ulonglong2 bb = *(const ulonglong2*)&ws[ci*68 + tx*4];
        ull p0 = pk2(av.x, av.x), p1 = pk2(av.y, av.y);
        ull p2 = pk2(av.z, av.z), p3 = pk2(av.w, av.w);
        fma2(acc[0][0], p0, bb.x); fma2(acc[0][1], p0, bb.y);
        fma2(acc[1][0], p1, bb.x); fma2(acc[1][1], p1, bb.y);
        fma2(acc[2][0], p2, bb.x); fma2(acc[2][1], p2, bb.y);
        fma2(acc[3][0], p3, bb.x); fma2(acc[3][1], p3, bb.y);
    }
    float4 bb4 = *(const float4*)&b2[tx*4];
    float* V = g_V[side];
    #pragma unroll
    for (int pj = 0; pj < 4; pj++) {
        int p = ty*4 + pj;
        float2 o01 = unpk(acc[pj][0]);
        float2 o23 = unpk(acc[pj][1]);
        float4 o; o.x = o01.x+bb4.x; o.y = o01.y+bb4.y;
                  o.z = o23.x+bb4.z; o.w = o23.y+bb4.w;
        *(float4*)&V[((size_t)((b*Hn + h)*Wn + w0 + p))*64 + tx*4] = o;
    }
}

// ---------------- dilated conv via mma.sync bf16 ---------------------------
// smem: strip [2 split][144 rows][72 bf16] + weights [6 tiles][64][72] + zred
#define STRIP_ELE (144*72)
#define WT_ELE    (64*72)
#define SMEM_CONV ((2*STRIP_ELE + 6*WT_ELE)*2 + 256)

__global__ void __launch_bounds__(256, 2) conv_mma_kernel(int side, const float* __restrict__ db) {
    extern __shared__ __nv_bfloat16 smc[];
    __nv_bfloat16* strip = smc;                 // [split][row][72]
    __nv_bfloat16* wts   = smc + 2*STRIP_ELE;   // [kx*2+split][co][72]
    float* zred = (float*)(wts + 6*WT_ELE);
    int t = threadIdx.x, lane = t & 31, warp = t >> 5;
    int w0 = blockIdx.x*128, h = blockIdx.y;
    int bm = blockIdx.z; int m = bm & 3, b = bm >> 2;
    int d = 2*(m+1), S = 128 + 2*d;
    if (t < 64) zred[t] = 0.f;

    float acc[8][4];
    #pragma unroll
    for (int g = 0; g < 8; g++) { acc[g][0]=acc[g][1]=acc[g][2]=acc[g][3]=0.f; }

    uint32_t strip_u = smem_u32(strip);
    uint32_t wts_u   = smem_u32(wts);
    // per-lane ldmatrix geometry
    int a_r  = ((lane >> 3) & 1)*8 + (lane & 7);
    int a_kh = lane >> 4;
    int b_n  = (lane >> 4)*8 + (lane & 7);
    int b_kh = (lane >> 3) & 1;

    const __nv_bfloat16* lnh = g_lnh[side];
    const __nv_bfloat16* lnl = g_lnl[side];

    for (int ky = 0; ky < 3; ky++) {
        int hy = h + (ky-1)*d;
        if ((unsigned)hy >= (unsigned)Hn) continue;
        __syncthreads();
        // load halo strip (hi/lo)
        size_t rb = ((size_t)(b*Hn + hy)*Wn)*64;
        for (int lin = t; lin < S*16; lin += 256) {
            int split = (lin >= S*8) ? 1 : 0;
            int rem = lin - split*S*8;
            int row = rem >> 3, cg = rem & 7;
            int px = w0 - d + row;
            uint4 v = make_uint4(0u,0u,0u,0u);
            if ((unsigned)px < (unsigned)Wn)
                v = *(const uint4*)((split ? lnl : lnh) + rb + (size_t)px*64 + cg*8);
            *(uint4*)&strip[split*STRIP_ELE + row*72 + cg*8] = v;
        }
        // load weights for this ky: 3 kx x 2 splits, verbatim rows -> padded rows
        const __nv_bfloat16* wsrc = g_w2 + (size_t)(((side*4 + m)*9 + ky*3)*2)*4096;
        for (int lin = t; lin < 3072; lin += 256) {
            int tile = lin >> 9, rem = lin & 511;
            int row = rem >> 3, cg = rem & 7;
            uint4 v = *(const uint4*)(wsrc + (size_t)tile*4096 + row*64 + cg*8);
            *(uint4*)&wts[tile*WT_ELE + row*72 + cg*8] = v;
        }
        __syncthreads();
        for (int kx = 0; kx < 3; kx++) {
            int rowbase = warp*16 + kx*d;
            uint32_t aAh = strip_u + (uint32_t)(((rowbase + a_r)*72 + a_kh*8)*2);
            uint32_t aAl = aAh + STRIP_ELE*2;
            uint32_t wBh = wts_u + (uint32_t)((((kx*2+0)*64 + b_n)*72 + b_kh*8)*2);
            uint32_t wBl = wts_u + (uint32_t)((((kx*2+1)*64 + b_n)*72 + b_kh*8)*2);
            #pragma unroll
            for (int ch = 0; ch < 4; ch++) {
                uint32_t ah[4], al[4], bh[16], bl[16];
                LDSM4(ah, aAh + ch*32);
                LDSM4(al, aAl + ch*32);
                #pragma unroll
                for (int g2 = 0; g2 < 4; g2++) {
                    LDSM4(bh + g2*4, wBh + g2*16*72*2 + ch*32);
                    LDSM4(bl + g2*4, wBl + g2*16*72*2 + ch*32);
                }
                #pragma unroll
                for (int g = 0; g < 8; g++) {
                    MMA_BF16(acc[g], ah, bh[2*g], bh[2*g+1]);
                    MMA_BF16(acc[g], ah, bl[2*g], bl[2*g+1]);
                    MMA_BF16(acc[g], al, bh[2*g], bh[2*g+1]);
                }
            }
        }
    }
    // epilogue: bias, store D, pooled-sum reduction
    int r = lane >> 2, c2 = (lane & 3)*2;
    int px0 = w0 + warp*16 + r;
    float* Dp = g_D[side] + (size_t)m*NELEM + ((size_t)((b*Hn + h)*Wn))*64;
    #pragma unroll
    for (int g = 0; g < 8; g++) {
        int c = g*8 + c2;
        float b0 = db[m*64 + c], b1 = db[m*64 + c + 1];
        float v00 = acc[g][0] + b0, v01 = acc[g][1] + b1;
        float v10 = acc[g][2] + b0, v11 = acc[g][3] + b1;
        *(float2*)&Dp[(size_t)px0*64 + c]     = make_float2(v00, v01);
        *(float2*)&Dp[(size_t)(px0+8)*64 + c] = make_float2(v10, v11);
        float s0 = v00 + v10, s1 = v01 + v11;
        #pragma unroll
        for (int o = 4; o < 32; o <<= 1) {
            s0 += __shfl_xor_sync(0xffffffffu, s0, o);
            s1 += __shfl_xor_sync(0xffffffffu, s1, o);
        }
        if (lane < 4 && lane == (c2 >> 1)) {
            atomicAdd(&zred[c], s0);
            atomicAdd(&zred[c+1], s1);
        }
    }
    __syncthreads();
    if (t < 64) atomicAdd(&g_Z[side][b*64 + t], zred[t]);
}

// ---------------- SKM gating -----------------------------------------------
__global__ void sw_kernel(int side, const float* __restrict__ c1w,
                          const float* __restrict__ c1b, const float* __restrict__ pw) {
    __shared__ float Zn[64], Sv[128], lg[256], eb[256], mx[4], sm[4];
    int b = blockIdx.x, t = threadIdx.x;
    if (t < 64) Zn[t] = g_Z[side][b*64 + t] * (1.f/(float)HW);
    __syncthreads();
    if (t < 128) {
        float s = c1b[t];
        #pragma unroll 8
        for (int c = 0; c < 64; c++) s += Zn[c]*c1w[t*64 + c];
        Sv[t] = fmaxf(s, 0.f);
    }
    __syncthreads();
    {
        float s = 0.f;
        #pragma unroll 8
        for (int j = 0; j < 128; j++) s += Sv[j]*pw[j*256 + t];
        lg[t] = s;
    }
    __syncthreads();
    if (t < 4) {
        float mm = -1e30f;
        for (int i = 0; i < 64; i++) mm = fmaxf(mm, lg[t*64 + i]);
        mx[t] = mm;
    }
    __syncthreads();
    eb[t] = __expf(lg[t] - mx[t >> 6]);
    __syncthreads();
    if (t < 4) {
        float s = 0.f;
        for (int i = 0; i < 64; i++) s += eb[t*64 + i];
        sm[t] = s;
    }
    __syncthreads();
    g_Sw[side][b*256 + t] = eb[t] / sm[t >> 6];
}

// ---------------- branch combine -------------------------------------------
__global__ void combine_kernel(int side) {
    size_t idx = (size_t)blockIdx.x*256 + threadIdx.x;
    if (idx >= NELEM) return;
    int c = (int)(idx & 63);
    int b = (int)(idx / ((size_t)HW*64));
    const float* D = g_D[side];
    const float* Sw = g_Sw[side];
    float s = 0.f;
    #pragma unroll
    for (int m = 0; m < Mn; m++)
        s += Sw[b*256 + m*64 + c] * D[(size_t)m*NELEM + idx];
    g_Q[side][idx] = s;
}

// ---------------- cross attention ------------------------------------------
__global__ void attn_kernel(int qa_side, const float* __restrict__ xres,
                            const float* __restrict__ svec, float* __restrict__ out) {
    extern __shared__ float fsm[];
    float* Qbs = fsm;                   // 256*66
    float* Vbs = Qbs + 256*66;          // 256*64
    float* qas = Vbs + 256*64;          // 8*256
    float* ps  = qas + 8*256;           // 8*1024
    int bh = blockIdx.x;
    int b = bh / Hn, h = bh % Hn;
    const float* Qap = g_Q[qa_side]     + (size_t)bh*Wn*64;
    const float* Qbp = g_Q[1 - qa_side] + (size_t)bh*Wn*64;
    const float* Vbp = g_V[1 - qa_side] + (size_t)bh*Wn*64;
    int t = threadIdx.x, lane = t & 31, warp = t >> 5;

    for (int k = 0; k < 64; k++) {
        int lin = t + 256*k;
        int v = lin >> 6, c = lin & 63;
        Qbs[v*66 + c] = Qbp[lin];
        Vbs[lin] = Vbp[lin];
    }
    __syncthreads();

    const float scale = 0.125f;
    for (int grp = 0; grp < 8; grp++) {
        int rbase = warp*32 + grp*4;
        #pragma unroll
        for (int j = 0; j < 4; j++) {
            qas[warp*256 + lane*4 + j]      = Qap[(rbase+j)*64 + lane];
            qas[warp*256 + (lane+32)*4 + j] = Qap[(rbase+j)*64 + lane + 32];
        }
        __syncwarp();
        ull sp[4][8];
        #pragma unroll
        for (int r = 0; r < 4; r++)
            #pragma unroll
            for (int j = 0; j < 8; j++) sp[r][j] = 0ull;
        #pragma unroll 4
        for (int cc = 0; cc < 64; cc += 2) {
            float4 fa = *(const float4*)&qas[warp*256 + cc*4];
            float4 fb = *(const float4*)&qas[warp*256 + (cc+1)*4];
            ull q0 = pk2(fa.x, fb.x), q1 = pk2(fa.y, fb.y);
            ull q2 = pk2(fa.z, fb.z), q3 = pk2(fa.w, fb.w);
            #pragma unroll
            for (int j = 0; j < 8; j++) {
                ull qb2 = *(const ull*)&Qbs[(lane + 32*j)*66 + cc];
                fma2(sp[0][j], q0, qb2);
                fma2(sp[1][j], q1, qb2);
                fma2(sp[2][j], q2, qb2);
                fma2(sp[3][j], q3, qb2);
            }
        }
        float s[4][8];
        #pragma unroll
        for (int r = 0; r < 4; r++)
            #pragma unroll
            for (int j = 0; j < 8; j++) {
                float2 u = unpk(sp[r][j]);
                s[r][j] = u.x + u.y;
            }
        float p[4][8];
        #pragma unroll
        for (int r = 0; r < 4; r++) {
            float mx = -1e30f;
            #pragma unroll
            for (int j = 0; j < 8; j++) { s[r][j] *= scale; mx = fmaxf(mx, s[r][j]); }
            #pragma unroll
            for (int o = 16; o > 0; o >>= 1) mx = fmaxf(mx, __shfl_xor_sync(0xffffffffu, mx, o));
            float sum = 0.f;
            #pragma unroll
            for (int j = 0; j < 8; j++) { float e = __expf(s[r][j] - mx); p[r][j] = e; sum += e; }
            #pragma unroll
            for (int o = 16; o > 0; o >>= 1) sum += __shfl_xor_sync(0xffffffffu, sum, o);
            float inv = __frcp_rn(sum);
            #pragma unroll
            for (int j = 0; j < 8; j++) p[r][j] *= inv;
        }
        #pragma unroll
        for (int j = 0; j < 8; j++) {
            int v = lane + 32*j;
            float4 pv; pv.x = p[0][j]; pv.y = p[1][j]; pv.z = p[2][j]; pv.w = p[3][j];
            *(float4*)&ps[warp*1024 + v*4] = pv;
        }
        __syncwarp();
        int c0 = lane*2;
        ull o0 = 0ull, o1 = 0ull, o2 = 0ull, o3 = 0ull;
        #pragma unroll 8
        for (int v = 0; v < 256; v++) {
            float4 pv = *(const float4*)&ps[warp*1024 + v*4];
            ull vb = *(const ull*)&Vbs[v*64 + c0];
            fma2(o0, pk2(pv.x, pv.x), vb);
            fma2(o1, pk2(pv.y, pv.y), vb);
            fma2(o2, pk2(pv.z, pv.z), vb);
            fma2(o3, pk2(pv.w, pv.w), vb);
        }
        float2 r0 = unpk(o0), r1 = unpk(o1), r2 = unpk(o2), r3 = unpk(o3);
        float sc0 = svec[c0], sc1 = svec[c0+1];
        float ro[4][2] = {{r0.x,r0.y},{r1.x,r1.y},{r2.x,r2.y},{r3.x,r3.y}};
        #pragma unroll
        for (int r = 0; r < 4; r++) {
            int w = rbase + r;
            size_t i0 = ((size_t)(b*64 + c0)*Hn + h)*Wn + w;
            out[i0] = xres[i0] + sc0*ro[r][0];
            size_t i1 = i0 + (size_t)HW;
            out[i1] = xres[i1] + sc1*ro[r][1];
        }
    }
}

// ---------------- launch ----------------------------------------------------
extern "C" void kernel_launch(void* const* d_in, const int* in_sizes, int n_in,
                              void* d_out, int out_size) {
    const float* x_l   = (const float*)d_in[0];
    const float* x_r   = (const float*)d_in[1];
    const float* lnl_g = (const float*)d_in[2];
    const float* lnl_b = (const float*)d_in[3];
    const float* lnr_g = (const float*)d_in[4];
    const float* lnr_b = (const float*)d_in[5];
    const float* l_dw  = (const float*)d_in[6];
    const float* l_db  = (const float*)d_in[7];
    const float* l_c1w = (const float*)d_in[8];
    const float* l_c1b = (const float*)d_in[9];
    const float* l_pw  = (const float*)d_in[10];
    const float* r_dw  = (const float*)d_in[11];
    const float* r_db  = (const float*)d_in[12];
    const float* r_c1w = (const float*)d_in[13];
    const float* r_c1b = (const float*)d_in[14];
    const float* r_pw  = (const float*)d_in[15];
    const float* l2w   = (const float*)d_in[16];
    const float* l2b   = (const float*)d_in[17];
    const float* r2w   = (const float*)d_in[18];
    const float* r2b   = (const float*)d_in[19];
    const float* beta  = (const float*)d_in[20];
    const float* gamma = (const float*)d_in[21];
    float* out_l = (float*)d_out;
    float* out_r = out_l + (size_t)NELEM;

    const int attn_smem = (256*66 + 256*64 + 8*256 + 8*1024) * 4;
    cudaFuncSetAttribute(attn_kernel, cudaFuncAttributeMaxDynamicSharedMemorySize, attn_smem);
    cudaFuncSetAttribute(conv_mma_kernel, cudaFuncAttributeMaxDynamicSharedMemorySize, SMEM_CONV);

    zero_z_kernel<<<1, 512>>>();
    wtrans_kernel<<<(2*Mn*9*Cn*Cn + 255)/256, 256>>>(l_dw, r_dw);

    dim3 tgrid(Wn/64, Hn, Bn);
    ln_kernel<<<tgrid, 256>>>(x_l, lnl_g, lnl_b, 0);
    ln_kernel<<<tgrid, 256>>>(x_r, lnr_g, lnr_b, 1);
    v_kernel<<<tgrid, 256>>>(x_l, l2w, l2b, 0);
    v_kernel<<<tgrid, 256>>>(x_r, r2w, r2b, 1);

    dim3 cgrid(Wn/128, Hn, Bn*Mn);
    conv_mma_kernel<<<cgrid, 256, SMEM_CONV>>>(0, l_db);
    conv_mma_kernel<<<cgrid, 256, SMEM_CONV>>>(1, r_db);

    sw_kernel<<<Bn, 256>>>(0, l_c1w, l_c1b, l_pw);
    sw_kernel<<<Bn, 256>>>(1, r_c1w, r_c1b, r_pw);

    combine_kernel<<<(NELEM + 255)/256, 256>>>(0);
    combine_kernel<<<(NELEM + 255)/256, 256>>>(1);

    attn_kernel<<<Bn*Hn, 256, attn_smem>>>(0, x_l, beta,  out_l);
    attn_kernel<<<Bn*Hn, 256, attn_smem>>>(1, x_r, gamma, out_r);
}

// round 7
// speedup vs baseline: 4.8429x; 2.6677x over previous
#include <cuda_runtime.h>
#include <cuda_fp16.h>
#include <math.h>
#include <cstdint>

#define Bn 4
#define Cn 64
#define Hn 96
#define Wn 256
#define Mn 4
#define HW (Hn*Wn)
#define NPIX (Bn*Hn*Wn)
#define NELEM (NPIX*Cn)

typedef unsigned long long ull;

// ---------------- f32x2 helpers (V path) -----------------------------------
__device__ __forceinline__ ull pk2(float a, float b) {
    ull r; asm("mov.b64 %0, {%1,%2};" : "=l"(r) : "f"(a), "f"(b)); return r;
}
__device__ __forceinline__ void fma2(ull& d, ull a, ull b) {
    asm("fma.rn.f32x2 %0, %1, %2, %3;" : "=l"(d) : "l"(a), "l"(b), "l"(d));
}
__device__ __forceinline__ float2 unpk(ull v) {
    float2 f; asm("mov.b64 {%0,%1}, %2;" : "=f"(f.x), "=f"(f.y) : "l"(v)); return f;
}

// ---------------- mma helpers ----------------------------------------------
__device__ __forceinline__ uint32_t smem_u32(const void* p) {
    uint32_t a;
    asm("{ .reg .u64 t; cvta.to.shared.u64 t, %1; cvt.u32.u64 %0, t; }" : "=r"(a) : "l"(p));
    return a;
}
#define LDSM4(r, addr) \
    asm volatile("ldmatrix.sync.aligned.m8n8.x4.shared.b16 {%0,%1,%2,%3}, [%4];" \
        : "=r"((r)[0]), "=r"((r)[1]), "=r"((r)[2]), "=r"((r)[3]) : "r"(addr))
#define LDSM4T(r, addr) \
    asm volatile("ldmatrix.sync.aligned.m8n8.x4.trans.shared.b16 {%0,%1,%2,%3}, [%4];" \
        : "=r"((r)[0]), "=r"((r)[1]), "=r"((r)[2]), "=r"((r)[3]) : "r"(addr))
#define MMA_F16(ac, a, b0_, b1_) \
    asm volatile("mma.sync.aligned.m16n8k16.row.col.f32.f16.f16.f32 " \
        "{%0,%1,%2,%3},{%4,%5,%6,%7},{%8,%9},{%0,%1,%2,%3};" \
        : "+f"((ac)[0]), "+f"((ac)[1]), "+f"((ac)[2]), "+f"((ac)[3]) \
        : "r"((a)[0]), "r"((a)[1]), "r"((a)[2]), "r"((a)[3]), "r"(b0_), "r"(b1_))
// pack two fp32 (hi,lo) -> f16x2, then 2^x on both halves
__device__ __forceinline__ uint32_t exp2pair(float hi, float lo) {
    uint32_t h, r;
    asm("cvt.rn.f16x2.f32 %0, %1, %2;" : "=r"(h) : "f"(hi), "f"(lo));
    asm("ex2.approx.f16x2 %0, %1;" : "=r"(r) : "r"(h));
    return r;
}

// ---------------- scratch (device globals) ---------------------------------
__device__ half g_lnx[2][NELEM];      // LN output fp16 NHWC
__device__ half g_w2h[2*4*9*4096];    // conv weights fp16 [side][m][tap][co][ci]
__device__ half g_Dh[2][Mn*NELEM];    // conv branches fp16 NHWC
__device__ half g_Qh[2][NELEM];       // Q fp16 NHWC
__device__ half g_VT[2][NELEM];       // V fp16 transposed [bh][c][w]
__device__ float g_Z[2][Bn*Cn];
__device__ float g_Sw[2][Bn*Mn*Cn];

// ---------------- zero pooled sums -----------------------------------------
__global__ void zero_z_kernel() {
    int t = threadIdx.x;
    if (t < 2*Bn*Cn) (&g_Z[0][0])[t] = 0.f;
}

// ---------------- weight transform -----------------------------------------
__global__ void wtrans_kernel(const float* __restrict__ ldw,
                              const float* __restrict__ rdw) {
    int t = blockIdx.x*blockDim.x + threadIdx.x;
    const int n = Mn*9*Cn*Cn;
    if (t >= 2*n) return;
    int side = t / n, i = t % n;
    const float* src = side ? rdw : ldw;
    int ci = i & 63; int r = i >> 6;
    int co = r & 63; r >>= 6;
    int tap = r % 9; int m = r / 9;
    int ky = tap / 3, kx = tap % 3;
    float wv = src[((((m*Cn + co)*Cn + ci)*3 + ky)*3 + kx)];
    g_w2h[(size_t)(((side*4 + m)*9 + tap))*4096 + co*64 + ci] = __float2half(wv);
}

// ---------------- LayerNorm2d: NCHW -> fp16 NHWC ---------------------------
__global__ void ln_kernel(const float* __restrict__ x, const float* __restrict__ g,
                          const float* __restrict__ bia, int side) {
    __shared__ float xs[64*65];
    __shared__ float mu_s[64], rs_s[64];
    int w0 = blockIdx.x*64, h = blockIdx.y, b = blockIdx.z;
    int t = threadIdx.x;
    const float* xp = x + (size_t)b*Cn*HW + (size_t)h*Wn + w0;
    #pragma unroll
    for (int k = 0; k < 16; k++) {
        int lin = t + 256*k; int c = lin >> 6, p = lin & 63;
        xs[c*65 + p] = xp[(size_t)c*HW + p];
    }
    __syncthreads();
    if (t < 64) {
        float s = 0.f, s2 = 0.f;
        #pragma unroll
        for (int c = 0; c < 64; c++) { float v = xs[c*65 + t]; s += v; s2 += v*v; }
        float mu = s * (1.f/64.f);
        float var = s2 * (1.f/64.f) - mu*mu;
        mu_s[t] = mu; rs_s[t] = rsqrtf(var + 1e-6f);
    }
    __syncthreads();
    half* op = g_lnx[side] + ((size_t)((b*Hn + h)*Wn + w0))*64;
    #pragma unroll
    for (int k = 0; k < 16; k++) {
        int lin = t + 256*k; int p = lin >> 6, c = lin & 63;
        float v = (xs[c*65 + p] - mu_s[p]) * rs_s[p] * g[c] + bia[c];
        op[p*64 + c] = __float2half(v);
    }
}

// ---------------- 1x1 conv V: NCHW x -> fp16 VT [bh][c][w] -----------------
__global__ void v_kernel(const float* __restrict__ x, const float* __restrict__ w2,
                         const float* __restrict__ b2, int side) {
    __shared__ float xs[64*68];
    __shared__ float ws[64*68];
    __shared__ half vs[64*72];   // [c][p]
    int w0 = blockIdx.x*64, h = blockIdx.y, b = blockIdx.z;
    int t = threadIdx.x, tx = t & 15, ty = t >> 4;
    const float* xp = x + (size_t)b*Cn*HW + (size_t)h*Wn + w0;
    #pragma unroll
    for (int k = 0; k < 16; k++) {
        int lin = t + 256*k; int ci = lin >> 6, p = lin & 63;
        xs[ci*68 + p] = xp[(size_t)ci*HW + p];
    }
    #pragma unroll
    for (int k = 0; k < 16; k++) {
        int lin = t + 256*k; int co = lin >> 6, ci = lin & 63;
        ws[ci*68 + co] = w2[co*64 + ci];
    }
    __syncthreads();
    ull acc[4][2];
    #pragma unroll
    for (int i = 0; i < 4; i++) { acc[i][0] = 0ull; acc[i][1] = 0ull; }
    #pragma unroll 8
    for (int ci = 0; ci < 64; ci++) {
        float4 av = *(const float4*)&xs[ci*68 + ty*4];
        ulonglong2 bb = *(const ulonglong2*)&ws[ci*68 + tx*4];
        ull p0 = pk2(av.x, av.x), p1 = pk2(av.y, av.y);
        ull p2 = pk2(av.z, av.z), p3 = pk2(av.w, av.w);
        fma2(acc[0][0], p0, bb.x); fma2(acc[0][1], p0, bb.y);
        fma2(acc[1][0], p1, bb.x); fma2(acc[1][1], p1, bb.y);
        fma2(acc[2][0], p2, bb.x); fma2(acc[2][1], p2, bb.y);
        fma2(acc[3][0], p3, bb.x); fma2(acc[3][1], p3, bb.y);
    }
    float4 bb4 = *(const float4*)&b2[tx*4];
    #pragma unroll
    for (int pj = 0; pj < 4; pj++) {
        int p = ty*4 + pj;
        float2 o01 = unpk(acc[pj][0]);
        float2 o23 = unpk(acc[pj][1]);
        vs[(tx*4+0)*72 + p] = __float2half(o01.x + bb4.x);
        vs[(tx*4+1)*72 + p] = __float2half(o01.y + bb4.y);
        vs[(tx*4+2)*72 + p] = __float2half(o23.x + bb4.z);
        vs[(tx*4+3)*72 + p] = __float2half(o23.y + bb4.w);
    }
    __syncthreads();
    half* VT = g_VT[side] + (size_t)(b*Hn + h)*64*Wn;
    // FIXED: full 64 rows x 64 cols = 512 uint4 (was writing only half)
    for (int lin = t; lin < 512; lin += 256) {
        int row = lin >> 3, seg = lin & 7;
        uint4 v = *(const uint4*)&vs[row*72 + seg*8];
        *(uint4*)&VT[row*Wn + w0 + seg*8] = v;
    }
}

// ---------------- dilated conv via mma.sync fp16 (single term) -------------
#define STRIP_S 72
#define WT_S 72
__global__ void __launch_bounds__(256) conv_mma_kernel(int side, const float* __restrict__ db) {
    __shared__ half strip[144*STRIP_S];
    __shared__ half wts[3*64*WT_S];
    __shared__ float zred[64];
    int t = threadIdx.x, lane = t & 31, warp = t >> 5;
    int w0 = blockIdx.x*128, h = blockIdx.y;
    int bm = blockIdx.z; int m = bm & 3, b = bm >> 2;
    int d = 2*(m+1), S = 128 + 2*d;
    if (t < 64) zred[t] = 0.f;

    float acc[8][4];
    #pragma unroll
    for (int g = 0; g < 8; g++) { acc[g][0]=acc[g][1]=acc[g][2]=acc[g][3]=0.f; }

    uint32_t strip_u = smem_u32(strip);
    uint32_t wts_u   = smem_u32(wts);
    int a_r  = ((lane >> 3) & 1)*8 + (lane & 7);
    int a_kh = lane >> 4;
    int b_n  = (lane >> 4)*8 + (lane & 7);
    int b_kh = (lane >> 3) & 1;

    const half* lnx = g_lnx[side];

    for (int ky = 0; ky < 3; ky++) {
        int hy = h + (ky-1)*d;
        if ((unsigned)hy >= (unsigned)Hn) continue;
        __syncthreads();
        size_t rb = ((size_t)(b*Hn + hy)*Wn)*64;
        for (int lin = t; lin < S*8; lin += 256) {
            int row = lin >> 3, cg = lin & 7;
            int px = w0 - d + row;
            uint4 v = make_uint4(0u,0u,0u,0u);
            if ((unsigned)px < (unsigned)Wn)
                v = *(const uint4*)(lnx + rb + (size_t)px*64 + cg*8);
            *(uint4*)&strip[row*STRIP_S + cg*8] = v;
        }
        const half* wsrc = g_w2h + (size_t)((side*4 + m)*9 + ky*3)*4096;
        for (int lin = t; lin < 1536; lin += 256) {
            int tile = lin >> 9, rem = lin & 511;
            int row = rem >> 3, cg = rem & 7;
            uint4 v = *(const uint4*)(wsrc + (size_t)tile*4096 + row*64 + cg*8);
            *(uint4*)&wts[tile*64*WT_S + row*WT_S + cg*8] = v;
        }
        __syncthreads();
        for (int kx = 0; kx < 3; kx++) {
            int rowbase = warp*16 + kx*d;
            uint32_t aA = strip_u + (uint32_t)(((rowbase + a_r)*STRIP_S + a_kh*8)*2);
            uint32_t wB = wts_u + (uint32_t)(((kx*64 + b_n)*WT_S + b_kh*8)*2);
            #pragma unroll
            for (int ch = 0; ch < 4; ch++) {
                uint32_t af[4], bf[16];
                LDSM4(af, aA + ch*32);
                #pragma unroll
                for (int g2 = 0; g2 < 4; g2++)
                    LDSM4(bf + g2*4, wB + g2*16*WT_S*2 + ch*32);
                #pragma unroll
                for (int g = 0; g < 8; g++)
                    MMA_F16(acc[g], af, bf[2*g], bf[2*g+1]);
            }
        }
    }
    int r = lane >> 2, c2 = (lane & 3)*2;
    int px0 = w0 + warp*16 + r;
    half* Dp = g_Dh[side] + (size_t)m*NELEM + ((size_t)((b*Hn + h)*Wn))*64;
    #pragma unroll
    for (int g = 0; g < 8; g++) {
        int c = g*8 + c2;
        float b0 = db[m*64 + c], b1 = db[m*64 + c + 1];
        float v00 = acc[g][0] + b0, v01 = acc[g][1] + b1;
        float v10 = acc[g][2] + b0, v11 = acc[g][3] + b1;
        *(half2*)&Dp[(size_t)px0*64 + c]     = __floats2half2_rn(v00, v01);
        *(half2*)&Dp[(size_t)(px0+8)*64 + c] = __floats2half2_rn(v10, v11);
        float s0 = v00 + v10, s1 = v01 + v11;
        #pragma unroll
        for (int o = 4; o < 32; o <<= 1) {
            s0 += __shfl_xor_sync(0xffffffffu, s0, o);
            s1 += __shfl_xor_sync(0xffffffffu, s1, o);
        }
        if (lane < 4 && lane == (c2 >> 1)) {
            atomicAdd(&zred[c], s0);
            atomicAdd(&zred[c+1], s1);
        }
    }
    __syncthreads();
    if (t < 64) atomicAdd(&g_Z[side][b*64 + t], zred[t]);
}

// ---------------- SKM gating -----------------------------------------------
__global__ void sw_kernel(int side, const float* __restrict__ c1w,
                          const float* __restrict__ c1b, const float* __restrict__ pw) {
    __shared__ float Zn[64], Sv[128], lg[256], eb[256], mx[4], sm[4];
    int b = blockIdx.x, t = threadIdx.x;
    if (t < 64) Zn[t] = g_Z[side][b*64 + t] * (1.f/(float)HW);
    __syncthreads();
    if (t < 128) {
        float s = c1b[t];
        #pragma unroll 8
        for (int c = 0; c < 64; c++) s += Zn[c]*c1w[t*64 + c];
        Sv[t] = fmaxf(s, 0.f);
    }
    __syncthreads();
    {
        float s = 0.f;
        #pragma unroll 8
        for (int j = 0; j < 128; j++) s += Sv[j]*pw[j*256 + t];
        lg[t] = s;
    }
    __syncthreads();
    if (t < 4) {
        float mm = -1e30f;
        for (int i = 0; i < 64; i++) mm = fmaxf(mm, lg[t*64 + i]);
        mx[t] = mm;
    }
    __syncthreads();
    eb[t] = __expf(lg[t] - mx[t >> 6]);
    __syncthreads();
    if (t < 4) {
        float s = 0.f;
        for (int i = 0; i < 64; i++) s += eb[t*64 + i];
        sm[t] = s;
    }
    __syncthreads();
    g_Sw[side][b*256 + t] = eb[t] / sm[t >> 6];
}

// ---------------- branch combine: D fp16 -> Q fp16 -------------------------
__global__ void combine_kernel(int side) {
    size_t idx2 = (size_t)blockIdx.x*256 + threadIdx.x;
    if (idx2 >= NELEM/2) return;
    int c2i = (int)(idx2 & 31);
    int b = (int)(idx2 / ((size_t)HW*32));
    const half2* Dh = (const half2*)g_Dh[side];
    const float* Sw = g_Sw[side] + b*256;
    float sx = 0.f, sy = 0.f;
    #pragma unroll
    for (int m = 0; m < Mn; m++) {
        float2 f = __half22float2(Dh[(size_t)m*(NELEM/2) + idx2]);
        sx += f.x * Sw[m*64 + c2i*2];
        sy += f.y * Sw[m*64 + c2i*2 + 1];
    }
    ((half2*)g_Qh[side])[idx2] = __floats2half2_rn(sx, sy);
}

// ---------------- fused cross attention (both directions) ------------------
#define EST 264
#define ASMEM (256*EST*2 + 2*256*72*2 + 4*1024 + 64)
__global__ void __launch_bounds__(256, 1) attn_kernel(
        const float* __restrict__ x_l, const float* __restrict__ x_r,
        const float* __restrict__ beta, const float* __restrict__ gamma,
        float* __restrict__ out_l, float* __restrict__ out_r) {
    extern __shared__ char smx[];
    half* E  = (half*)smx;                 // [256][EST] exp(s - rowmax)
    half* Qa = E + 256*EST;
    half* Qb = Qa + 256*72;
    half* VTr = Qa;                        // union with Q
    half* VTl = Qa + 64*EST;
    float* rowsum = (float*)(smx + 256*EST*2 + 2*256*72*2);
    float* colsum = rowsum + 256;
    float* rowmax = colsum + 256;
    float* alpha  = rowmax + 256;
    float* red    = alpha + 256;
    int bh = blockIdx.x;
    int b = bh / Hn, h = bh % Hn;
    int t = threadIdx.x, lane = t & 31, warp = t >> 5;
    uint32_t Eu = smem_u32(E), Qau = smem_u32(Qa), Qbu = smem_u32(Qb);
    uint32_t VTru = smem_u32(VTr), VTlu = smem_u32(VTl);

    int a_r  = ((lane >> 3) & 1)*8 + (lane & 7);
    int a_kh = lane >> 4;
    int b_n  = (lane >> 4)*8 + (lane & 7);
    int b_kh = (lane >> 3) & 1;
    int e_r  = (lane & 7) + (lane >> 4)*8;   // trans-A row
    int e_kh = (lane >> 3) & 1;

    const half* Qlp = g_Qh[0] + (size_t)bh*Wn*64;
    const half* Qrp = g_Qh[1] + (size_t)bh*Wn*64;
    for (int lin = t; lin < 2048; lin += 256) {
        int row = lin >> 3, cg = lin & 7;
        *(uint4*)&Qa[row*72 + cg*8] = *(const uint4*)(Qlp + row*64 + cg*8);
        *(uint4*)&Qb[row*72 + cg*8] = *(const uint4*)(Qrp + row*64 + cg*8);
    }
    __syncthreads();

    // Phase 1: S = Ql.Qr^T (fp32 regs) -> per-row max -> exp (f16x2) -> E, rowsum
    const float K = 0.125f * 1.44269504f;   // scale * log2e
    int r = lane >> 2, c2l = (lane & 3)*2;
    for (int pass = 0; pass < 2; pass++) {
        int wbase = pass*128 + warp*16;
        float acc[32][4];
        #pragma unroll
        for (int i = 0; i < 32; i++) { acc[i][0]=acc[i][1]=acc[i][2]=acc[i][3]=0.f; }
        #pragma unroll
        for (int k = 0; k < 4; k++) {
            uint32_t af[4];
            LDSM4(af, Qau + (uint32_t)(((wbase + a_r)*72 + k*16 + a_kh*8)*2));
            #pragma unroll
            for (int g2 = 0; g2 < 16; g2++) {
                uint32_t bf[4];
                LDSM4(bf, Qbu + (uint32_t)(((g2*16 + b_n)*72 + k*16 + b_kh*8)*2));
                MMA_F16(acc[2*g2],   af, bf[0], bf[1]);
                MMA_F16(acc[2*g2+1], af, bf[2], bf[3]);
            }
        }
        // per-row max over quad (rows wbase+r and wbase+r+8, raw acc units)
        float m0 = -1e30f, m1 = -1e30f;
        #pragma unroll
        for (int ti = 0; ti < 32; ti++) {
            m0 = fmaxf(m0, fmaxf(acc[ti][0], acc[ti][1]));
            m1 = fmaxf(m1, fmaxf(acc[ti][2], acc[ti][3]));
        }
        m0 = fmaxf(m0, __shfl_xor_sync(0xffffffffu, m0, 1));
        m0 = fmaxf(m0, __shfl_xor_sync(0xffffffffu, m0, 2));
        m1 = fmaxf(m1, __shfl_xor_sync(0xffffffffu, m1, 1));
        m1 = fmaxf(m1, __shfl_xor_sync(0xffffffffu, m1, 2));
        float rs0 = 0.f, rs1 = 0.f;
        #pragma unroll
        for (int ti = 0; ti < 32; ti++) {
            int v = ti*8 + c2l;
            uint32_t e0 = exp2pair((acc[ti][1]-m0)*K, (acc[ti][0]-m0)*K);
            uint32_t e1 = exp2pair((acc[ti][3]-m1)*K, (acc[ti][2]-m1)*K);
            *(uint32_t*)&E[(wbase+r)*EST + v]   = e0;
            *(uint32_t*)&E[(wbase+r+8)*EST + v] = e1;
            float2 f0 = __half22float2(*(half2*)&e0);
            float2 f1 = __half22float2(*(half2*)&e1);
            rs0 += f0.x + f0.y;
            rs1 += f1.x + f1.y;
        }
        rs0 += __shfl_xor_sync(0xffffffffu, rs0, 1);
        rs0 += __shfl_xor_sync(0xffffffffu, rs0, 2);
        rs1 += __shfl_xor_sync(0xffffffffu, rs1, 1);
        rs1 += __shfl_xor_sync(0xffffffffu, rs1, 2);
        if ((lane & 3) == 0) {
            rowsum[wbase+r] = rs0;   rowmax[wbase+r] = m0;
            rowsum[wbase+r+8] = rs1; rowmax[wbase+r+8] = m1;
        }
    }
    __syncthreads();
    // global max g over rowmax; alpha_w = 2^((m_w - g)*K)
    if (warp == 0) {
        float gm = -1e30f;
        #pragma unroll
        for (int i = 0; i < 8; i++) gm = fmaxf(gm, rowmax[lane + i*32]);
        #pragma unroll
        for (int o = 16; o > 0; o >>= 1) gm = fmaxf(gm, __shfl_xor_sync(0xffffffffu, gm, o));
        if (lane == 0) red[0] = gm;
    }
    __syncthreads();
    alpha[t] = exp2f((rowmax[t] - red[0]) * K);
    __syncthreads();
    // weighted col sums + load VT tiles (VTl scaled by alpha rows)
    {
        float cs = 0.f;
        #pragma unroll 8
        for (int rr = 0; rr < 256; rr++) cs += __half2float(E[rr*EST + t]) * alpha[rr];
        colsum[t] = cs;
    }
    const half* Vlp = g_VT[0] + (size_t)bh*64*Wn;
    const half* Vrp = g_VT[1] + (size_t)bh*64*Wn;
    for (int lin = t; lin < 2048; lin += 256) {
        int row = lin >> 5, seg = lin & 31;
        *(uint4*)&VTr[row*EST + seg*8] = *(const uint4*)(Vrp + row*Wn + seg*8);
        uint4 v = *(const uint4*)(Vlp + row*Wn + seg*8);
        half2* hp = (half2*)&v;
        #pragma unroll
        for (int i = 0; i < 4; i++) {
            float2 f = __half22float2(hp[i]);
            f.x *= alpha[seg*8 + 2*i];
            f.y *= alpha[seg*8 + 2*i + 1];
            hp[i] = __floats2half2_rn(f.x, f.y);
        }
        *(uint4*)&VTl[row*EST + seg*8] = v;
    }
    __syncthreads();

    // GEMM1: F_r2l = (E . VTr^T) / rowsum -> out_l
    for (int pass = 0; pass < 2; pass++) {
        int wbase = pass*128 + warp*16;
        float acc[8][4];
        #pragma unroll
        for (int i = 0; i < 8; i++) { acc[i][0]=acc[i][1]=acc[i][2]=acc[i][3]=0.f; }
        #pragma unroll 4
        for (int k = 0; k < 16; k++) {
            uint32_t af[4];
            LDSM4(af, Eu + (uint32_t)(((wbase + a_r)*EST + k*16 + a_kh*8)*2));
            #pragma unroll
            for (int g2 = 0; g2 < 4; g2++) {
                uint32_t bf[4];
                LDSM4(bf, VTru + (uint32_t)(((g2*16 + b_n)*EST + k*16 + b_kh*8)*2));
                MMA_F16(acc[2*g2],   af, bf[0], bf[1]);
                MMA_F16(acc[2*g2+1], af, bf[2], bf[3]);
            }
        }
        int w0r = wbase + r;
        float inv0 = __frcp_rn(rowsum[w0r]), inv1 = __frcp_rn(rowsum[w0r+8]);
        #pragma unroll
        for (int tile = 0; tile < 8; tile++) {
            int c = tile*8 + c2l;
            float bc0 = __ldg(&beta[c]), bc1 = __ldg(&beta[c+1]);
            size_t i00 = ((size_t)(b*64 + c)*Hn + h)*Wn + w0r;
            out_l[i00]      = x_l[i00]      + bc0*acc[tile][0]*inv0;
            out_l[i00+HW]   = x_l[i00+HW]   + bc1*acc[tile][1]*inv0;
            out_l[i00+8]    = x_l[i00+8]    + bc0*acc[tile][2]*inv1;
            out_l[i00+HW+8] = x_l[i00+HW+8] + bc1*acc[tile][3]*inv1;
        }
    }
    // GEMM2: F_l2r = (E^T . VTl'^T) / colsum -> out_r  (VTl' rows scaled by alpha)
    for (int pass = 0; pass < 2; pass++) {
        int vbase = pass*128 + warp*16;
        float acc[8][4];
        #pragma unroll
        for (int i = 0; i < 8; i++) { acc[i][0]=acc[i][1]=acc[i][2]=acc[i][3]=0.f; }
        #pragma unroll 4
        for (int k = 0; k < 16; k++) {
            uint32_t af[4];
            LDSM4T(af, Eu + (uint32_t)(((k*16 + e_r)*EST + vbase + e_kh*8)*2));
            #pragma unroll
            for (int g2 = 0; g2 < 4; g2++) {
                uint32_t bf[4];
                LDSM4(bf, VTlu + (uint32_t)(((g2*16 + b_n)*EST + k*16 + b_kh*8)*2));
                MMA_F16(acc[2*g2],   af, bf[0], bf[1]);
                MMA_F16(acc[2*g2+1], af, bf[2], bf[3]);
            }
        }
        int v0r = vbase + r;
        float inv0 = __frcp_rn(colsum[v0r]), inv1 = __frcp_rn(colsum[v0r+8]);
        #pragma unroll
        for (int tile = 0; tile < 8; tile++) {
            int c = tile*8 + c2l;
            float gc0 = __ldg(&gamma[c]), gc1 = __ldg(&gamma[c+1]);
            size_t i00 = ((size_t)(b*64 + c)*Hn + h)*Wn + v0r;
            out_r[i00]      = x_r[i00]      + gc0*acc[tile][0]*inv0;
            out_r[i00+HW]   = x_r[i00+HW]   + gc1*acc[tile][1]*inv0;
            out_r[i00+8]    = x_r[i00+8]    + gc0*acc[tile][2]*inv1;
            out_r[i00+HW+8] = x_r[i00+HW+8] + gc1*acc[tile][3]*inv1;
        }
    }
}

// ---------------- launch ----------------------------------------------------
extern "C" void kernel_launch(void* const* d_in, const int* in_sizes, int n_in,
                              void* d_out, int out_size) {
    const float* x_l   = (const float*)d_in[0];
    const float* x_r   = (const float*)d_in[1];
    const float* lnl_g = (const float*)d_in[2];
    const float* lnl_b = (const float*)d_in[3];
    const float* lnr_g = (const float*)d_in[4];
    const float* lnr_b = (const float*)d_in[5];
    const float* l_dw  = (const float*)d_in[6];
    const float* l_db  = (const float*)d_in[7];
    const float* l_c1w = (const float*)d_in[8];
    const float* l_c1b = (const float*)d_in[9];
    const float* l_pw  = (const float*)d_in[10];
    const float* r_dw  = (const float*)d_in[11];
    const float* r_db  = (const float*)d_in[12];
    const float* r_c1w = (const float*)d_in[13];
    const float* r_c1b = (const float*)d_in[14];
    const float* r_pw  = (const float*)d_in[15];
    const float* l2w   = (const float*)d_in[16];
    const float* l2b   = (const float*)d_in[17];
    const float* r2w   = (const float*)d_in[18];
    const float* r2b   = (const float*)d_in[19];
    const float* beta  = (const float*)d_in[20];
    const float* gamma = (const float*)d_in[21];
    float* out_l = (float*)d_out;
    float* out_r = out_l + (size_t)NELEM;

    cudaFuncSetAttribute(attn_kernel, cudaFuncAttributeMaxDynamicSharedMemorySize, ASMEM);

    zero_z_kernel<<<1, 512>>>();
    wtrans_kernel<<<(2*Mn*9*Cn*Cn + 255)/256, 256>>>(l_dw, r_dw);

    dim3 tgrid(Wn/64, Hn, Bn);
    ln_kernel<<<tgrid, 256>>>(x_l, lnl_g, lnl_b, 0);
    ln_kernel<<<tgrid, 256>>>(x_r, lnr_g, lnr_b, 1);
    v_kernel<<<tgrid, 256>>>(x_l, l2w, l2b, 0);
    v_kernel<<<tgrid, 256>>>(x_r, r2w, r2b, 1);

    dim3 cgrid(Wn/128, Hn, Bn*Mn);
    conv_mma_kernel<<<cgrid, 256>>>(0, l_db);
    conv_mma_kernel<<<cgrid, 256>>>(1, r_db);

    sw_kernel<<<Bn, 256>>>(0, l_c1w, l_c1b, l_pw);
    sw_kernel<<<Bn, 256>>>(1, r_c1w, r_c1b, r_pw);

    combine_kernel<<<(NELEM/2 + 255)/256, 256>>>(0);
    combine_kernel<<<(NELEM/2 + 255)/256, 256>>>(1);

    attn_kernel<<<Bn*Hn, 256, ASMEM>>>(x_l, x_r, beta, gamma, out_l, out_r);
}

// round 8
// speedup vs baseline: 4.9994x; 1.0323x over previous
#include <cuda_runtime.h>
#include <cuda_fp16.h>
#include <math.h>
#include <cstdint>

#define Bn 4
#define Cn 64
#define Hn 96
#define Wn 256
#define Mn 4
#define HW (Hn*Wn)
#define NPIX (Bn*Hn*Wn)
#define NELEM (NPIX*Cn)

typedef unsigned long long ull;

// ---------------- f32x2 helpers (V path) -----------------------------------
__device__ __forceinline__ ull pk2(float a, float b) {
    ull r; asm("mov.b64 %0, {%1,%2};" : "=l"(r) : "f"(a), "f"(b)); return r;
}
__device__ __forceinline__ void fma2(ull& d, ull a, ull b) {
    asm("fma.rn.f32x2 %0, %1, %2, %3;" : "=l"(d) : "l"(a), "l"(b), "l"(d));
}
__device__ __forceinline__ float2 unpk(ull v) {
    float2 f; asm("mov.b64 {%0,%1}, %2;" : "=f"(f.x), "=f"(f.y) : "l"(v)); return f;
}

// ---------------- mma helpers ----------------------------------------------
__device__ __forceinline__ uint32_t smem_u32(const void* p) {
    uint32_t a;
    asm("{ .reg .u64 t; cvta.to.shared.u64 t, %1; cvt.u32.u64 %0, t; }" : "=r"(a) : "l"(p));
    return a;
}
#define LDSM4(r, addr) \
    asm volatile("ldmatrix.sync.aligned.m8n8.x4.shared.b16 {%0,%1,%2,%3}, [%4];" \
        : "=r"((r)[0]), "=r"((r)[1]), "=r"((r)[2]), "=r"((r)[3]) : "r"(addr))
#define LDSM4T(r, addr) \
    asm volatile("ldmatrix.sync.aligned.m8n8.x4.trans.shared.b16 {%0,%1,%2,%3}, [%4];" \
        : "=r"((r)[0]), "=r"((r)[1]), "=r"((r)[2]), "=r"((r)[3]) : "r"(addr))
#define MMA_F16(ac, a, b0_, b1_) \
    asm volatile("mma.sync.aligned.m16n8k16.row.col.f32.f16.f16.f32 " \
        "{%0,%1,%2,%3},{%4,%5,%6,%7},{%8,%9},{%0,%1,%2,%3};" \
        : "+f"((ac)[0]), "+f"((ac)[1]), "+f"((ac)[2]), "+f"((ac)[3]) \
        : "r"((a)[0]), "r"((a)[1]), "r"((a)[2]), "r"((a)[3]), "r"(b0_), "r"(b1_))
// pack two fp32 (hi,lo) -> f16x2, then 2^x on both halves
__device__ __forceinline__ uint32_t exp2pair(float hi, float lo) {
    uint32_t h, r;
    asm("cvt.rn.f16x2.f32 %0, %1, %2;" : "=r"(h) : "f"(hi), "f"(lo));
    asm("ex2.approx.f16x2 %0, %1;" : "=r"(r) : "r"(h));
    return r;
}

// ---------------- scratch (device globals) ---------------------------------
__device__ half g_lnx[2][NELEM];      // LN output fp16 NHWC
__device__ half g_w2h[2*4*9*4096];    // conv weights fp16 [side][m][tap][co][ci]
__device__ half g_Dh[2][Mn*NELEM];    // conv branches fp16 NHWC
__device__ half g_Qh[2][NELEM];       // Q fp16 NHWC
__device__ half g_VT[2][NELEM];       // V fp16 transposed [bh][c][w]
__device__ float g_Z[2][Bn*Cn];
__device__ float g_Sw[2][Bn*Mn*Cn];

// ---------------- zero pooled sums -----------------------------------------
__global__ void zero_z_kernel() {
    int t = threadIdx.x;
    if (t < 2*Bn*Cn) (&g_Z[0][0])[t] = 0.f;
}

// ---------------- weight transform -----------------------------------------
__global__ void wtrans_kernel(const float* __restrict__ ldw,
                              const float* __restrict__ rdw) {
    int t = blockIdx.x*blockDim.x + threadIdx.x;
    const int n = Mn*9*Cn*Cn;
    if (t >= 2*n) return;
    int side = t / n, i = t % n;
    const float* src = side ? rdw : ldw;
    int ci = i & 63; int r = i >> 6;
    int co = r & 63; r >>= 6;
    int tap = r % 9; int m = r / 9;
    int ky = tap / 3, kx = tap % 3;
    float wv = src[((((m*Cn + co)*Cn + ci)*3 + ky)*3 + kx)];
    g_w2h[(size_t)(((side*4 + m)*9 + tap))*4096 + co*64 + ci] = __float2half(wv);
}

// ---------------- fused LayerNorm2d + 1x1 V projection ---------------------
// x NCHW tile -> lnx fp16 NHWC, VT fp16 [bh][c][w]
__global__ void lnv_kernel(const float* __restrict__ x,
                           const float* __restrict__ g, const float* __restrict__ bia,
                           const float* __restrict__ w2, const float* __restrict__ b2,
                           int side) {
    __shared__ float xs[64*68];   // [ci][p]
    __shared__ float ws[64*68];   // [ci][co]
    __shared__ half  vs[64*72];   // [c][p]
    __shared__ float part[4*64];
    __shared__ float mu_s[64], rs_s[64];
    int w0 = blockIdx.x*64, h = blockIdx.y, b = blockIdx.z;
    int t = threadIdx.x, tx = t & 15, ty = t >> 4;
    const float* xp = x + (size_t)b*Cn*HW + (size_t)h*Wn + w0;
    #pragma unroll
    for (int k = 0; k < 16; k++) {
        int lin = t + 256*k; int ci = lin >> 6, p = lin & 63;
        xs[ci*68 + p] = xp[(size_t)ci*HW + p];
    }
    #pragma unroll
    for (int k = 0; k < 16; k++) {
        int lin = t + 256*k; int co = lin >> 6, ci = lin & 63;
        ws[ci*68 + co] = w2[co*64 + ci];
    }
    __syncthreads();
    // LN stats: 4 quarter-partials per pixel column
    {
        int q = t >> 6, p = t & 63;
        float s = 0.f, s2 = 0.f;
        #pragma unroll
        for (int i = 0; i < 16; i++) {
            float v = xs[(q*16 + i)*68 + p];
            s += v; s2 += v*v;
        }
        part[q*64 + p] = s;
        part[q*64 + p + 256 - 256] = s;   // keep layout simple: store s now, s2 after sync via second array
        // use two halves of part by reusing mu_s/rs_s as scratch for s2
        ((float*)vs)[q*64 + p] = s2;      // vs unused yet; borrow as fp32 scratch (4*64 floats = 1KB < 9KB)
    }
    __syncthreads();
    if (t < 64) {
        float s  = part[t] + part[64+t] + part[128+t] + part[192+t];
        float* s2p = (float*)vs;
        float s2 = s2p[t] + s2p[64+t] + s2p[128+t] + s2p[192+t];
        float mu = s * (1.f/64.f);
        float var = s2 * (1.f/64.f) - mu*mu;
        mu_s[t] = mu; rs_s[t] = rsqrtf(var + 1e-6f);
    }
    __syncthreads();
    // LN write (fp16 NHWC)
    half* op = g_lnx[side] + ((size_t)((b*Hn + h)*Wn + w0))*64;
    #pragma unroll
    for (int k = 0; k < 16; k++) {
        int lin = t + 256*k; int p = lin >> 6, c = lin & 63;
        float v = (xs[c*68 + p] - mu_s[p]) * rs_s[p] * g[c] + bia[c];
        op[p*64 + c] = __float2half(v);
    }
    // V = W2 x + b2 (f32x2 GEMM on the same xs tile)
    ull acc[4][2];
    #pragma unroll
    for (int i = 0; i < 4; i++) { acc[i][0] = 0ull; acc[i][1] = 0ull; }
    #pragma unroll 8
    for (int ci = 0; ci < 64; ci++) {
        float4 av = *(const float4*)&xs[ci*68 + ty*4];
        ulonglong2 bb = *(const ulonglong2*)&ws[ci*68 + tx*4];
        ull p0 = pk2(av.x, av.x), p1 = pk2(av.y, av.y);
        ull p2 = pk2(av.z, av.z), p3 = pk2(av.w, av.w);
        fma2(acc[0][0], p0, bb.x); fma2(acc[0][1], p0, bb.y);
        fma2(acc[1][0], p1, bb.x); fma2(acc[1][1], p1, bb.y);
        fma2(acc[2][0], p2, bb.x); fma2(acc[2][1], p2, bb.y);
        fma2(acc[3][0], p3, bb.x); fma2(acc[3][1], p3, bb.y);
    }
    __syncthreads();   // vs scratch (s2) no longer needed
    float4 bb4 = *(const float4*)&b2[tx*4];
    #pragma unroll
    for (int pj = 0; pj < 4; pj++) {
        int p = ty*4 + pj;
        float2 o01 = unpk(acc[pj][0]);
        float2 o23 = unpk(acc[pj][1]);
        vs[(tx*4+0)*72 + p] = __float2half(o01.x + bb4.x);
        vs[(tx*4+1)*72 + p] = __float2half(o01.y + bb4.y);
        vs[(tx*4+2)*72 + p] = __float2half(o23.x + bb4.z);
        vs[(tx*4+3)*72 + p] = __float2half(o23.y + bb4.w);
    }
    __syncthreads();
    half* VT = g_VT[side] + (size_t)(b*Hn + h)*64*Wn;
    for (int lin = t; lin < 512; lin += 256) {
        int row = lin >> 3, seg = lin & 7;
        uint4 v = *(const uint4*)&vs[row*72 + seg*8];
        *(uint4*)&VT[row*Wn + w0 + seg*8] = v;
    }
}

// ---------------- dilated conv via mma.sync fp16 (single term) -------------
#define STRIP_S 72
#define WT_S 72
__global__ void __launch_bounds__(256) conv_mma_kernel(int side, const float* __restrict__ db) {
    __shared__ half strip[144*STRIP_S];
    __shared__ half wts[3*64*WT_S];
    __shared__ float zred[64];
    int t = threadIdx.x, lane = t & 31, warp = t >> 5;
    int w0 = blockIdx.x*128, h = blockIdx.y;
    int bm = blockIdx.z; int m = bm & 3, b = bm >> 2;
    int d = 2*(m+1), S = 128 + 2*d;
    if (t < 64) zred[t] = 0.f;

    float acc[8][4];
    #pragma unroll
    for (int g = 0; g < 8; g++) { acc[g][0]=acc[g][1]=acc[g][2]=acc[g][3]=0.f; }

    uint32_t strip_u = smem_u32(strip);
    uint32_t wts_u   = smem_u32(wts);
    int a_r  = ((lane >> 3) & 1)*8 + (lane & 7);
    int a_kh = lane >> 4;
    int b_n  = (lane >> 4)*8 + (lane & 7);
    int b_kh = (lane >> 3) & 1;

    const half* lnx = g_lnx[side];

    for (int ky = 0; ky < 3; ky++) {
        int hy = h + (ky-1)*d;
        if ((unsigned)hy >= (unsigned)Hn) continue;
        __syncthreads();
        size_t rb = ((size_t)(b*Hn + hy)*Wn)*64;
        for (int lin = t; lin < S*8; lin += 256) {
            int row = lin >> 3, cg = lin & 7;
            int px = w0 - d + row;
            uint4 v = make_uint4(0u,0u,0u,0u);
            if ((unsigned)px < (unsigned)Wn)
                v = *(const uint4*)(lnx + rb + (size_t)px*64 + cg*8);
            *(uint4*)&strip[row*STRIP_S + cg*8] = v;
        }
        const half* wsrc = g_w2h + (size_t)((side*4 + m)*9 + ky*3)*4096;
        for (int lin = t; lin < 1536; lin += 256) {
            int tile = lin >> 9, rem = lin & 511;
            int row = rem >> 3, cg = rem & 7;
            uint4 v = *(const uint4*)(wsrc + (size_t)tile*4096 + row*64 + cg*8);
            *(uint4*)&wts[tile*64*WT_S + row*WT_S + cg*8] = v;
        }
        __syncthreads();
        for (int kx = 0; kx < 3; kx++) {
            int rowbase = warp*16 + kx*d;
            uint32_t aA = strip_u + (uint32_t)(((rowbase + a_r)*STRIP_S + a_kh*8)*2);
            uint32_t wB = wts_u + (uint32_t)(((kx*64 + b_n)*WT_S + b_kh*8)*2);
            #pragma unroll
            for (int ch = 0; ch < 4; ch++) {
                uint32_t af[4], bf[16];
                LDSM4(af, aA + ch*32);
                #pragma unroll
                for (int g2 = 0; g2 < 4; g2++)
                    LDSM4(bf + g2*4, wB + g2*16*WT_S*2 + ch*32);
                #pragma unroll
                for (int g = 0; g < 8; g++)
                    MMA_F16(acc[g], af, bf[2*g], bf[2*g+1]);
            }
        }
    }
    int r = lane >> 2, c2 = (lane & 3)*2;
    int px0 = w0 + warp*16 + r;
    half* Dp = g_Dh[side] + (size_t)m*NELEM + ((size_t)((b*Hn + h)*Wn))*64;
    #pragma unroll
    for (int g = 0; g < 8; g++) {
        int c = g*8 + c2;
        float b0 = db[m*64 + c], b1 = db[m*64 + c + 1];
        float v00 = acc[g][0] + b0, v01 = acc[g][1] + b1;
        float v10 = acc[g][2] + b0, v11 = acc[g][3] + b1;
        *(half2*)&Dp[(size_t)px0*64 + c]     = __floats2half2_rn(v00, v01);
        *(half2*)&Dp[(size_t)(px0+8)*64 + c] = __floats2half2_rn(v10, v11);
        float s0 = v00 + v10, s1 = v01 + v11;
        #pragma unroll
        for (int o = 4; o < 32; o <<= 1) {
            s0 += __shfl_xor_sync(0xffffffffu, s0, o);
            s1 += __shfl_xor_sync(0xffffffffu, s1, o);
        }
        if (lane < 4 && lane == (c2 >> 1)) {
            atomicAdd(&zred[c], s0);
            atomicAdd(&zred[c+1], s1);
        }
    }
    __syncthreads();
    if (t < 64) atomicAdd(&g_Z[side][b*64 + t], zred[t]);
}

// ---------------- SKM gating -----------------------------------------------
__global__ void sw_kernel(int side, const float* __restrict__ c1w,
                          const float* __restrict__ c1b, const float* __restrict__ pw) {
    __shared__ float Zn[64], Sv[128], lg[256], eb[256], mx[4], sm[4];
    int b = blockIdx.x, t = threadIdx.x;
    if (t < 64) Zn[t] = g_Z[side][b*64 + t] * (1.f/(float)HW);
    __syncthreads();
    if (t < 128) {
        float s = c1b[t];
        #pragma unroll 8
        for (int c = 0; c < 64; c++) s += Zn[c]*c1w[t*64 + c];
        Sv[t] = fmaxf(s, 0.f);
    }
    __syncthreads();
    {
        float s = 0.f;
        #pragma unroll 8
        for (int j = 0; j < 128; j++) s += Sv[j]*pw[j*256 + t];
        lg[t] = s;
    }
    __syncthreads();
    if (t < 4) {
        float mm = -1e30f;
        for (int i = 0; i < 64; i++) mm = fmaxf(mm, lg[t*64 + i]);
        mx[t] = mm;
    }
    __syncthreads();
    eb[t] = __expf(lg[t] - mx[t >> 6]);
    __syncthreads();
    if (t < 4) {
        float s = 0.f;
        for (int i = 0; i < 64; i++) s += eb[t*64 + i];
        sm[t] = s;
    }
    __syncthreads();
    g_Sw[side][b*256 + t] = eb[t] / sm[t >> 6];
}

// ---------------- branch combine: D fp16 -> Q fp16 -------------------------
__global__ void combine_kernel(int side) {
    size_t idx2 = (size_t)blockIdx.x*256 + threadIdx.x;
    if (idx2 >= NELEM/2) return;
    int c2i = (int)(idx2 & 31);
    int b = (int)(idx2 / ((size_t)HW*32));
    const half2* Dh = (const half2*)g_Dh[side];
    const float* Sw = g_Sw[side] + b*256;
    float sx = 0.f, sy = 0.f;
    #pragma unroll
    for (int m = 0; m < Mn; m++) {
        float2 f = __half22float2(Dh[(size_t)m*(NELEM/2) + idx2]);
        sx += f.x * Sw[m*64 + c2i*2];
        sy += f.y * Sw[m*64 + c2i*2 + 1];
    }
    ((half2*)g_Qh[side])[idx2] = __floats2half2_rn(sx, sy);
}

// ---------------- fused cross attention (both directions) ------------------
#define EST 264
#define ASMEM (256*EST*2 + 2*256*72*2 + 4*1024 + 64)
__global__ void __launch_bounds__(256, 1) attn_kernel(
        const float* __restrict__ x_l, const float* __restrict__ x_r,
        const float* __restrict__ beta, const float* __restrict__ gamma,
        float* __restrict__ out_l, float* __restrict__ out_r) {
    extern __shared__ char smx[];
    half* E  = (half*)smx;                 // [256][EST] exp(s - rowmax)
    half* Qa = E + 256*EST;
    half* Qb = Qa + 256*72;
    half* VTr = Qa;                        // union with Q
    half* VTl = Qa + 64*EST;
    float* rowsum = (float*)(smx + 256*EST*2 + 2*256*72*2);
    float* colsum = rowsum + 256;
    float* rowmax = colsum + 256;
    float* alpha  = rowmax + 256;
    float* red    = alpha + 256;
    int bh = blockIdx.x;
    int b = bh / Hn, h = bh % Hn;
    int t = threadIdx.x, lane = t & 31, warp = t >> 5;
    uint32_t Eu = smem_u32(E), Qau = smem_u32(Qa), Qbu = smem_u32(Qb);
    uint32_t VTru = smem_u32(VTr), VTlu = smem_u32(VTl);

    int a_r  = ((lane >> 3) & 1)*8 + (lane & 7);
    int a_kh = lane >> 4;
    int b_n  = (lane >> 4)*8 + (lane & 7);
    int b_kh = (lane >> 3) & 1;
    int e_r  = (lane & 7) + (lane >> 4)*8;   // trans-A row
    int e_kh = (lane >> 3) & 1;

    const half* Qlp = g_Qh[0] + (size_t)bh*Wn*64;
    const half* Qrp = g_Qh[1] + (size_t)bh*Wn*64;
    for (int lin = t; lin < 2048; lin += 256) {
        int row = lin >> 3, cg = lin & 7;
        *(uint4*)&Qa[row*72 + cg*8] = *(const uint4*)(Qlp + row*64 + cg*8);
        *(uint4*)&Qb[row*72 + cg*8] = *(const uint4*)(Qrp + row*64 + cg*8);
    }
    __syncthreads();

    // Phase 1: S = Ql.Qr^T (fp32 regs) -> per-row max -> exp (f16x2) -> E, rowsum
    const float K = 0.125f * 1.44269504f;   // scale * log2e
    int r = lane >> 2, c2l = (lane & 3)*2;
    for (int pass = 0; pass < 2; pass++) {
        int wbase = pass*128 + warp*16;
        float acc[32][4];
        #pragma unroll
        for (int i = 0; i < 32; i++) { acc[i][0]=acc[i][1]=acc[i][2]=acc[i][3]=0.f; }
        #pragma unroll
        for (int k = 0; k < 4; k++) {
            uint32_t af[4];
            LDSM4(af, Qau + (uint32_t)(((wbase + a_r)*72 + k*16 + a_kh*8)*2));
            #pragma unroll
            for (int g2 = 0; g2 < 16; g2++) {
                uint32_t bf[4];
                LDSM4(bf, Qbu + (uint32_t)(((g2*16 + b_n)*72 + k*16 + b_kh*8)*2));
                MMA_F16(acc[2*g2],   af, bf[0], bf[1]);
                MMA_F16(acc[2*g2+1], af, bf[2], bf[3]);
            }
        }
        // per-row max over quad (rows wbase+r and wbase+r+8, raw acc units)
        float m0 = -1e30f, m1 = -1e30f;
        #pragma unroll
        for (int ti = 0; ti < 32; ti++) {
            m0 = fmaxf(m0, fmaxf(acc[ti][0], acc[ti][1]));
            m1 = fmaxf(m1, fmaxf(acc[ti][2], acc[ti][3]));
        }
        m0 = fmaxf(m0, __shfl_xor_sync(0xffffffffu, m0, 1));
        m0 = fmaxf(m0, __shfl_xor_sync(0xffffffffu, m0, 2));
        m1 = fmaxf(m1, __shfl_xor_sync(0xffffffffu, m1, 1));
        m1 = fmaxf(m1, __shfl_xor_sync(0xffffffffu, m1, 2));
        float rs0 = 0.f, rs1 = 0.f;
        #pragma unroll
        for (int ti = 0; ti < 32; ti++) {
            int v = ti*8 + c2l;
            uint32_t e0 = exp2pair((acc[ti][1]-m0)*K, (acc[ti][0]-m0)*K);
            uint32_t e1 = exp2pair((acc[ti][3]-m1)*K, (acc[ti][2]-m1)*K);
            *(uint32_t*)&E[(wbase+r)*EST + v]   = e0;
            *(uint32_t*)&E[(wbase+r+8)*EST + v] = e1;
            float2 f0 = __half22float2(*(half2*)&e0);
            float2 f1 = __half22float2(*(half2*)&e1);
            rs0 += f0.x + f0.y;
            rs1 += f1.x + f1.y;
        }
        rs0 += __shfl_xor_sync(0xffffffffu, rs0, 1);
        rs0 += __shfl_xor_sync(0xffffffffu, rs0, 2);
        rs1 += __shfl_xor_sync(0xffffffffu, rs1, 1);
        rs1 += __shfl_xor_sync(0xffffffffu, rs1, 2);
        if ((lane & 3) == 0) {
            rowsum[wbase+r] = rs0;   rowmax[wbase+r] = m0;
            rowsum[wbase+r+8] = rs1; rowmax[wbase+r+8] = m1;
        }
    }
    __syncthreads();
    // global max g over rowmax; alpha_w = 2^((m_w - g)*K)
    if (warp == 0) {
        float gm = -1e30f;
        #pragma unroll
        for (int i = 0; i < 8; i++) gm = fmaxf(gm, rowmax[lane + i*32]);
        #pragma unroll
        for (int o = 16; o > 0; o >>= 1) gm = fmaxf(gm, __shfl_xor_sync(0xffffffffu, gm, o));
        if (lane == 0) red[0] = gm;
    }
    __syncthreads();
    alpha[t] = exp2f((rowmax[t] - red[0]) * K);
    __syncthreads();
    // weighted col sums + load VT tiles (VTl scaled by alpha rows)
    {
        float cs = 0.f;
        #pragma unroll 8
        for (int rr = 0; rr < 256; rr++) cs += __half2float(E[rr*EST + t]) * alpha[rr];
        colsum[t] = cs;
    }
    const half* Vlp = g_VT[0] + (size_t)bh*64*Wn;
    const half* Vrp = g_VT[1] + (size_t)bh*64*Wn;
    for (int lin = t; lin < 2048; lin += 256) {
        int row = lin >> 5, seg = lin & 31;
        *(uint4*)&VTr[row*EST + seg*8] = *(const uint4*)(Vrp + row*Wn + seg*8);
        uint4 v = *(const uint4*)(Vlp + row*Wn + seg*8);
        half2* hp = (half2*)&v;
        #pragma unroll
        for (int i = 0; i < 4; i++) {
            float2 f = __half22float2(hp[i]);
            f.x *= alpha[seg*8 + 2*i];
            f.y *= alpha[seg*8 + 2*i + 1];
            hp[i] = __floats2half2_rn(f.x, f.y);
        }
        *(uint4*)&VTl[row*EST + seg*8] = v;
    }
    __syncthreads();

    // GEMM1: F_r2l = (E . VTr^T) / rowsum -> out_l
    for (int pass = 0; pass < 2; pass++) {
        int wbase = pass*128 + warp*16;
        float acc[8][4];
        #pragma unroll
        for (int i = 0; i < 8; i++) { acc[i][0]=acc[i][1]=acc[i][2]=acc[i][3]=0.f; }
        #pragma unroll 4
        for (int k = 0; k < 16; k++) {
            uint32_t af[4];
            LDSM4(af, Eu + (uint32_t)(((wbase + a_r)*EST + k*16 + a_kh*8)*2));
            #pragma unroll
            for (int g2 = 0; g2 < 4; g2++) {
                uint32_t bf[4];
                LDSM4(bf, VTru + (uint32_t)(((g2*16 + b_n)*EST + k*16 + b_kh*8)*2));
                MMA_F16(acc[2*g2],   af, bf[0], bf[1]);
                MMA_F16(acc[2*g2+1], af, bf[2], bf[3]);
            }
        }
        int w0r = wbase + r;
        float inv0 = __frcp_rn(rowsum[w0r]), inv1 = __frcp_rn(rowsum[w0r+8]);
        #pragma unroll
        for (int tile = 0; tile < 8; tile++) {
            int c = tile*8 + c2l;
            float bc0 = __ldg(&beta[c]), bc1 = __ldg(&beta[c+1]);
            size_t i00 = ((size_t)(b*64 + c)*Hn + h)*Wn + w0r;
            out_l[i00]      = x_l[i00]      + bc0*acc[tile][0]*inv0;
            out_l[i00+HW]   = x_l[i00+HW]   + bc1*acc[tile][1]*inv0;
            out_l[i00+8]    = x_l[i00+8]    + bc0*acc[tile][2]*inv1;
            out_l[i00+HW+8] = x_l[i00+HW+8] + bc1*acc[tile][3]*inv1;
        }
    }
    // GEMM2: F_l2r = (E^T . VTl'^T) / colsum -> out_r  (VTl' rows scaled by alpha)
    for (int pass = 0; pass < 2; pass++) {
        int vbase = pass*128 + warp*16;
        float acc[8][4];
        #pragma unroll
        for (int i = 0; i < 8; i++) { acc[i][0]=acc[i][1]=acc[i][2]=acc[i][3]=0.f; }
        #pragma unroll 4
        for (int k = 0; k < 16; k++) {
            uint32_t af[4];
            LDSM4T(af, Eu + (uint32_t)(((k*16 + e_r)*EST + vbase + e_kh*8)*2));
            #pragma unroll
            for (int g2 = 0; g2 < 4; g2++) {
                uint32_t bf[4];
                LDSM4(bf, VTlu + (uint32_t)(((g2*16 + b_n)*EST + k*16 + b_kh*8)*2));
                MMA_F16(acc[2*g2],   af, bf[0], bf[1]);
                MMA_F16(acc[2*g2+1], af, bf[2], bf[3]);
            }
        }
        int v0r = vbase + r;
        float inv0 = __frcp_rn(colsum[v0r]), inv1 = __frcp_rn(colsum[v0r+8]);
        #pragma unroll
        for (int tile = 0; tile < 8; tile++) {
            int c = tile*8 + c2l;
            float gc0 = __ldg(&gamma[c]), gc1 = __ldg(&gamma[c+1]);
            size_t i00 = ((size_t)(b*64 + c)*Hn + h)*Wn + v0r;
            out_r[i00]      = x_r[i00]      + gc0*acc[tile][0]*inv0;
            out_r[i00+HW]   = x_r[i00+HW]   + gc1*acc[tile][1]*inv0;
            out_r[i00+8]    = x_r[i00+8]    + gc0*acc[tile][2]*inv1;
            out_r[i00+HW+8] = x_r[i00+HW+8] + gc1*acc[tile][3]*inv1;
        }
    }
}

// ---------------- launch ----------------------------------------------------
extern "C" void kernel_launch(void* const* d_in, const int* in_sizes, int n_in,
                              void* d_out, int out_size) {
    const float* x_l   = (const float*)d_in[0];
    const float* x_r   = (const float*)d_in[1];
    const float* lnl_g = (const float*)d_in[2];
    const float* lnl_b = (const float*)d_in[3];
    const float* lnr_g = (const float*)d_in[4];
    const float* lnr_b = (const float*)d_in[5];
    const float* l_dw  = (const float*)d_in[6];
    const float* l_db  = (const float*)d_in[7];
    const float* l_c1w = (const float*)d_in[8];
    const float* l_c1b = (const float*)d_in[9];
    const float* l_pw  = (const float*)d_in[10];
    const float* r_dw  = (const float*)d_in[11];
    const float* r_db  = (const float*)d_in[12];
    const float* r_c1w = (const float*)d_in[13];
    const float* r_c1b = (const float*)d_in[14];
    const float* r_pw  = (const float*)d_in[15];
    const float* l2w   = (const float*)d_in[16];
    const float* l2b   = (const float*)d_in[17];
    const float* r2w   = (const float*)d_in[18];
    const float* r2b   = (const float*)d_in[19];
    const float* beta  = (const float*)d_in[20];
    const float* gamma = (const float*)d_in[21];
    float* out_l = (float*)d_out;
    float* out_r = out_l + (size_t)NELEM;

    cudaFuncSetAttribute(attn_kernel, cudaFuncAttributeMaxDynamicSharedMemorySize, ASMEM);

    zero_z_kernel<<<1, 512>>>();                                   // launch 1
    wtrans_kernel<<<(2*Mn*9*Cn*Cn + 255)/256, 256>>>(l_dw, r_dw);  // launch 2

    dim3 tgrid(Wn/64, Hn, Bn);
    lnv_kernel<<<tgrid, 256>>>(x_l, lnl_g, lnl_b, l2w, l2b, 0);    // launch 3
    lnv_kernel<<<tgrid, 256>>>(x_r, lnr_g, lnr_b, r2w, r2b, 1);    // launch 4

    dim3 cgrid(Wn/128, Hn, Bn*Mn);
    conv_mma_kernel<<<cgrid, 256>>>(0, l_db);                      // launch 5
    conv_mma_kernel<<<cgrid, 256>>>(1, r_db);                      // launch 6 <- ncu capture

    sw_kernel<<<Bn, 256>>>(0, l_c1w, l_c1b, l_pw);
    sw_kernel<<<Bn, 256>>>(1, r_c1w, r_c1b, r_pw);

    combine_kernel<<<(NELEM/2 + 255)/256, 256>>>(0);
    combine_kernel<<<(NELEM/2 + 255)/256, 256>>>(1);

    attn_kernel<<<Bn*Hn, 256, ASMEM>>>(x_l, x_r, beta, gamma, out_l, out_r);
}